// round 7
// baseline (speedup 1.0000x reference)
#include <cuda_runtime.h>
#include <cstdint>

#define N_NODES 20000
#define N_EDGES 500000

// padded dims
#define MP   20032   // node rows padded
#define K1P  416     // zc width padded (400 -> 416)
#define ABW  832     // AB row stride: A in [0,416), B in [416,832)
#define N2P  224     // fc2 out padded (200 -> 224), 28 n8-tiles
#define N3P  128     // fc3 out padded (100 -> 128), 16 n8-tiles
#define TILE_E 128

// fragment-layout table sizes
#define W2F_TOTAL (13 * 4 * 28 * 64)   // 93184 floats
#define W3F_TOTAL (7 * 4 * 16 * 64)    // 28672 floats

// ---- scratch (static device globals; allocation-free) ----
__device__ float g_M[N_NODES * 16];
__device__ __align__(16) float g_ZC[MP * K1P];
__device__ __align__(16) float g_Wcat[K1P * ABW];
__device__ __align__(16) float g_AB[MP * ABW];       // ~67 MB, L2-resident
__device__ __align__(16) float g_W2f[W2F_TOTAL];     // fc2 weights, mma-fragment order
__device__ __align__(16) float g_W3f[W3F_TOTAL];     // fc3 weights, mma-fragment order

__device__ __forceinline__ float tf32r(float x) {
    asm("cvt.rna.tf32.f32 %0, %1;" : "=f"(x) : "f"(x));
    return x;
}

__device__ __forceinline__ void mma8(float c[4],
                                     uint32_t a0, uint32_t a1, uint32_t a2, uint32_t a3,
                                     uint32_t b0, uint32_t b1) {
    asm volatile(
        "mma.sync.aligned.m16n8k8.row.col.f32.tf32.tf32.f32 "
        "{%0,%1,%2,%3}, {%4,%5,%6,%7}, {%8,%9}, {%0,%1,%2,%3};"
        : "+f"(c[0]), "+f"(c[1]), "+f"(c[2]), "+f"(c[3])
        : "r"(a0), "r"(a1), "r"(a2), "r"(a3), "r"(b0), "r"(b1));
}

__device__ __forceinline__ void cp16(void* dst_smem, const void* src_gmem) {
    uint32_t d = (uint32_t)__cvta_generic_to_shared(dst_smem);
    asm volatile("cp.async.cg.shared.global [%0], [%1], 16;\n"
                 :: "r"(d), "l"(src_gmem));
}
#define CP_COMMIT() asm volatile("cp.async.commit_group;\n" ::: "memory")
#define CP_WAIT0()  asm volatile("cp.async.wait_group 0;\n" ::: "memory")

// ---- K0: build weight tables (Wcat for gemm_ab, W2f/W3f in fragment order) ----
__global__ void prep_weights(const float* __restrict__ fc1_w,
                             const float* __restrict__ fc2_w,
                             const float* __restrict__ fc3_w) {
    const int t1 = K1P * ABW, t2 = W2F_TOTAL, t3 = W3F_TOTAL;
    for (int i = blockIdx.x * blockDim.x + threadIdx.x; i < t1 + t2 + t3;
         i += gridDim.x * blockDim.x) {
        if (i < t1) {
            int k = i / ABW, j = i % ABW;
            float v = 0.f;
            if (k < 400) {
                if (j < 400) v = fc1_w[k * 400 + j];
                else if (j >= 416 && j < 816) v = fc1_w[(400 + k) * 400 + (j - 416)];
            }
            g_Wcat[i] = tf32r(v);
        } else if (i < t1 + t2) {
            // W2f layout: ((kt*4 + k8)*28 + nf)*64 + lane*2 + p
            int ii = i - t1;
            int p = ii & 1, lane = (ii >> 1) & 31;
            int r = ii >> 6;
            int nf = r % 28, k8 = (r / 28) & 3, kt = r / 112;
            int g = lane >> 2, t = lane & 3;
            int k = kt * 32 + k8 * 8 + t + 4 * p;
            int col = nf * 8 + g;
            float v = (k < 400 && col < 200) ? fc2_w[k * 200 + col] : 0.f;
            g_W2f[ii] = tf32r(v);
        } else {
            // W3f layout: ((kt3*4 + k8)*16 + nf)*64 + lane*2 + p ; K over 224, N over 128
            int ii = i - t1 - t2;
            int p = ii & 1, lane = (ii >> 1) & 31;
            int r = ii >> 6;
            int nf = r % 16, k8 = (r / 16) & 3, kt3 = r / 64;
            int g = lane >> 2, t = lane & 3;
            int k = kt3 * 32 + k8 * 8 + t + 4 * p;
            int col = nf * 8 + g;
            float v = (k < 200 && col < 100) ? fc3_w[k * 100 + col] : 0.f;
            g_W3f[ii] = tf32r(v);
        }
    }
}

// ---- K1: tiny per-node MLP 4->64->32->16 ----
__global__ void node_mlp(const float* __restrict__ cf,
                         const float* __restrict__ w1, const float* __restrict__ b1,
                         const float* __restrict__ w2, const float* __restrict__ b2,
                         const float* __restrict__ w3, const float* __restrict__ b3) {
    __shared__ float s_w1[4 * 64], s_b1[64], s_w2[64 * 32], s_b2[32], s_w3[32 * 16], s_b3[16];
    int tid = threadIdx.x;
    for (int i = tid; i < 256; i += blockDim.x)  s_w1[i] = w1[i];
    for (int i = tid; i < 64; i += blockDim.x)   s_b1[i] = b1[i];
    for (int i = tid; i < 2048; i += blockDim.x) s_w2[i] = w2[i];
    for (int i = tid; i < 32; i += blockDim.x)   s_b2[i] = b2[i];
    for (int i = tid; i < 512; i += blockDim.x)  s_w3[i] = w3[i];
    for (int i = tid; i < 16; i += blockDim.x)   s_b3[i] = b3[i];
    __syncthreads();
    int n = blockIdx.x * blockDim.x + tid;
    if (n >= N_NODES) return;
    float c0 = cf[n * 4], c1 = cf[n * 4 + 1], c2 = cf[n * 4 + 2], c3 = cf[n * 4 + 3];
    float h1[64];
#pragma unroll
    for (int j = 0; j < 64; j++) {
        float v = s_b1[j] + c0 * s_w1[j] + c1 * s_w1[64 + j] + c2 * s_w1[128 + j] + c3 * s_w1[192 + j];
        h1[j] = fmaxf(v, 0.f);
    }
    float h2[32];
    for (int j = 0; j < 32; j++) {
        float v = s_b2[j];
        for (int k = 0; k < 64; k++) v += h1[k] * s_w2[k * 32 + j];
        h2[j] = fmaxf(v, 0.f);
    }
    for (int j = 0; j < 16; j++) {
        float v = s_b3[j];
        for (int k = 0; k < 32; k++) v += h2[k] * s_w3[k * 16 + j];
        g_M[n * 16 + j] = v;
    }
}

// ---- K2: assemble padded zc = [z | m | esm | 0], tf32-rounded ----
__global__ void build_zc(const float* __restrict__ z, const float* __restrict__ esm) {
    const int total = MP * K1P;
    for (int i = blockIdx.x * blockDim.x + threadIdx.x; i < total;
         i += gridDim.x * blockDim.x) {
        int n = i / K1P, c = i % K1P;
        float v = 0.f;
        if (n < N_NODES) {
            if (c < 64) v = z[n * 64 + c];
            else if (c < 80) v = g_M[n * 16 + c - 64];
            else if (c < 400) v = esm[n * 320 + (c - 80)];
        }
        g_ZC[i] = tf32r(v);
    }
}

// ---- K3: AB = ZC @ Wcat  (tf32 mma, BM=64 BN=64 BK=32; conflict-free strides) ----
__global__ __launch_bounds__(256) void gemm_ab(const float* __restrict__ fc1_b) {
    __shared__ float As[64 * 36];
    __shared__ float Bs[32 * 72];
    int tid = threadIdx.x;
    int w = tid >> 5, lane = tid & 31;
    int g = lane >> 2, t = lane & 3;
    int wm = w & 3, wn = w >> 2;
    int m0 = blockIdx.y * 64;
    int n0 = blockIdx.x * 64;
    float acc[4][4] = {};

    for (int kt = 0; kt < K1P; kt += 32) {
        for (int i = tid; i < 64 * 8; i += 256) {
            int r = i >> 3, c4 = (i & 7) * 4;
            float4 v = *(const float4*)&g_ZC[(m0 + r) * K1P + kt + c4];
            As[r * 36 + c4] = v.x; As[r * 36 + c4 + 1] = v.y;
            As[r * 36 + c4 + 2] = v.z; As[r * 36 + c4 + 3] = v.w;
        }
        for (int i = tid; i < 32 * 16; i += 256) {
            int r = i >> 4, c4 = (i & 15) * 4;
            float4 v = *(const float4*)&g_Wcat[(kt + r) * ABW + n0 + c4];
            Bs[r * 72 + c4] = v.x; Bs[r * 72 + c4 + 1] = v.y;
            Bs[r * 72 + c4 + 2] = v.z; Bs[r * 72 + c4 + 3] = v.w;
        }
        __syncthreads();
#pragma unroll
        for (int k8 = 0; k8 < 4; k8++) {
            int kk = k8 * 8;
            int ar = wm * 16 + g;
            uint32_t a0 = __float_as_uint(As[ar * 36 + kk + t]);
            uint32_t a1 = __float_as_uint(As[(ar + 8) * 36 + kk + t]);
            uint32_t a2 = __float_as_uint(As[ar * 36 + kk + t + 4]);
            uint32_t a3 = __float_as_uint(As[(ar + 8) * 36 + kk + t + 4]);
#pragma unroll
            for (int nf = 0; nf < 4; nf++) {
                int col = wn * 32 + nf * 8 + g;
                uint32_t b0 = __float_as_uint(Bs[(kk + t) * 72 + col]);
                uint32_t b1 = __float_as_uint(Bs[(kk + t + 4) * 72 + col]);
                mma8(acc[nf], a0, a1, a2, a3, b0, b1);
            }
        }
        __syncthreads();
    }
#pragma unroll
    for (int nf = 0; nf < 4; nf++) {
#pragma unroll
        for (int i = 0; i < 4; i++) {
            int r = m0 + wm * 16 + g + ((i >> 1) ? 8 : 0);
            int col = n0 + wn * 32 + nf * 8 + 2 * t + (i & 1);
            float v = acc[nf][i];
            if (col < 400) v += __ldg(&fc1_b[col]);   // fold b1 into A half only
            g_AB[r * ABW + col] = v;
        }
    }
}

// ============================================================================
// K4: fused edge kernel — pipelined (cp.async weights, LDG-prefetch gather,
// ONE barrier per ktile), fragment-layout smem, 4m x 4n warp tiling.
//   smem word map (FIXED: h1 buffer stride is 4224 = full tile, x2 buffers):
//     h2f   [0, 29568)        : 224 blocks of 132 (fc3 A operand, frag order)
//     h1f   [29568, 38016)    : 2 buffers x 4224  (fc2 A operand, frag order)
//     wbuf  [38016, 52352)    : 2 x 7168 (fc2 W) / 2 x 4096 (fc3 W)
//     spart [52352, 52864)    : fc4 partials [4][128]
//     sw4   [52864, 52992)    : padded w4
//     ssrc  [52992, 53120)    : src indices (int)
//     sdst  [53120, 53248)    : dst indices (int)
// ============================================================================
#define SM_H2F   0
#define SM_H1F   29568
#define H1_STRIDE 4224
#define SM_WBUF  38016
#define SM_SPART 52352
#define SM_SW4   52864
#define SM_SRC   52992
#define SM_DST   53120
#define SM_WORDS 53248

__global__ __launch_bounds__(512, 1) void edge_kernel(
    const int* __restrict__ eidx,
    const float* __restrict__ b2, const float* __restrict__ b3,
    const float* __restrict__ w4, const float* __restrict__ b4v,
    float* __restrict__ out) {
    extern __shared__ float sm[];
    float* h2f = sm + SM_H2F;
    float* h1f = sm + SM_H1F;
    float* wbuf = sm + SM_WBUF;
    float* spart = sm + SM_SPART;
    float* sw4 = sm + SM_SW4;
    int* ssrc = (int*)(sm + SM_SRC);
    int* sdst = (int*)(sm + SM_DST);

    int tid = threadIdx.x;
    int w = tid >> 5, lane = tid & 31;
    int g = lane >> 2, t = lane & 3;
    int wm = w & 3, wn = w >> 2;   // 4 m-warps (32 rows each) x 4 n-warps
    int e0 = blockIdx.x * TILE_E;

    if (tid < TILE_E) {
        int e = e0 + tid;
        int s = 0, d = 0;
        if (e < N_EDGES) { s = eidx[e]; d = eidx[N_EDGES + e]; }
        s = min(max(s, 0), N_NODES - 1);
        d = min(max(d, 0), N_NODES - 1);
        ssrc[tid] = s; sdst[tid] = d;
        sw4[tid] = (tid < 100) ? __ldg(&w4[tid]) : 0.f;
    }
    __syncthreads();

    // gather-thread geometry: each thread owns (edge ge, k8 slice k8g)
    int ge = tid >> 2;
    int k8g = tid & 3;
    int gg = ge & 7, rpg = (ge >> 3) & 1, mtg_g = ge >> 4;
    int h1off = (mtg_g * 4 + k8g) * 132 + gg * 16 + rpg;
    const float* srowp = &g_AB[(size_t)ssrc[ge] * ABW];
    const float* drowp = &g_AB[(size_t)sdst[ge] * ABW + 416];
    int q = k8g * 8;

    float acc2[2][7][4] = {};

    // -------- prologue: stage tile 0 (gather + weights) --------
    {
        float4 a0 = *(const float4*)&srowp[q];
        float4 a1 = *(const float4*)&srowp[q + 4];
        float4 c0 = *(const float4*)&drowp[q];
        float4 c1 = *(const float4*)&drowp[q + 4];
        for (int j = tid; j < 1792; j += 512)
            cp16(&wbuf[j * 4], &g_W2f[j * 4]);
        CP_COMMIT();
        float* hw = &h1f[h1off];
        hw[0]  = tf32r(fmaxf(a0.x + c0.x, 0.f));
        hw[4]  = tf32r(fmaxf(a0.y + c0.y, 0.f));
        hw[8]  = tf32r(fmaxf(a0.z + c0.z, 0.f));
        hw[12] = tf32r(fmaxf(a0.w + c0.w, 0.f));
        hw[2]  = tf32r(fmaxf(a1.x + c1.x, 0.f));
        hw[6]  = tf32r(fmaxf(a1.y + c1.y, 0.f));
        hw[10] = tf32r(fmaxf(a1.z + c1.z, 0.f));
        hw[14] = tf32r(fmaxf(a1.w + c1.w, 0.f));
        CP_WAIT0();
    }
    __syncthreads();

    // ---------------- fc2: K=416 (13 ktiles of 32), N=224 ----------------
    for (int i = 0; i < 13; i++) {
        int b = i & 1;
        float4 a0, a1, c0, c1;
        if (i < 12) {   // prefetch tile i+1: gather -> regs, weights -> alt buffer
            int kt = (i + 1) * 32;
            a0 = *(const float4*)&srowp[kt + q];
            a1 = *(const float4*)&srowp[kt + q + 4];
            c0 = *(const float4*)&drowp[kt + q];
            c1 = *(const float4*)&drowp[kt + q + 4];
            const float* wsrc = &g_W2f[(i + 1) * 7168];
            float* wdst = &wbuf[(b ^ 1) * 7168];
            for (int j = tid; j < 1792; j += 512)
                cp16(&wdst[j * 4], &wsrc[j * 4]);
            CP_COMMIT();
        }
        const float* hbase = &h1f[b * H1_STRIDE];
        const float* wbase = &wbuf[b * 7168];
#pragma unroll
        for (int k8 = 0; k8 < 4; k8++) {
            float4 af0 = *(const float4*)&hbase[((wm * 2 + 0) * 4 + k8) * 132 + lane * 4];
            float4 af1 = *(const float4*)&hbase[((wm * 2 + 1) * 4 + k8) * 132 + lane * 4];
            uint32_t a00 = __float_as_uint(af0.x), a01 = __float_as_uint(af0.y);
            uint32_t a02 = __float_as_uint(af0.z), a03 = __float_as_uint(af0.w);
            uint32_t a10 = __float_as_uint(af1.x), a11 = __float_as_uint(af1.y);
            uint32_t a12 = __float_as_uint(af1.z), a13 = __float_as_uint(af1.w);
#pragma unroll
            for (int nf = 0; nf < 7; nf++) {
                float2 bf = *(const float2*)&wbase[((k8 * 28 + wn * 7 + nf) * 32 + lane) * 2];
                uint32_t b0 = __float_as_uint(bf.x), b1 = __float_as_uint(bf.y);
                mma8(acc2[0][nf], a00, a01, a02, a03, b0, b1);
                mma8(acc2[1][nf], a10, a11, a12, a13, b0, b1);
            }
        }
        if (i < 12) {   // commit prefetched gather into alt h1 buffer
            float* hw = &h1f[(b ^ 1) * H1_STRIDE + h1off];
            hw[0]  = tf32r(fmaxf(a0.x + c0.x, 0.f));
            hw[4]  = tf32r(fmaxf(a0.y + c0.y, 0.f));
            hw[8]  = tf32r(fmaxf(a0.z + c0.z, 0.f));
            hw[12] = tf32r(fmaxf(a0.w + c0.w, 0.f));
            hw[2]  = tf32r(fmaxf(a1.x + c1.x, 0.f));
            hw[6]  = tf32r(fmaxf(a1.y + c1.y, 0.f));
            hw[10] = tf32r(fmaxf(a1.z + c1.z, 0.f));
            hw[14] = tf32r(fmaxf(a1.w + c1.w, 0.f));
            CP_WAIT0();
        }
        __syncthreads();
    }

    // prefetch fc3 weights tile 0 (overlaps epilogue scatter below)
    for (int j = tid; j < 1024; j += 512)
        cp16(&wbuf[j * 4], &g_W3f[j * 4]);
    CP_COMMIT();

    // fc2 epilogue: bias + relu + tf32-round, scatter into h2f (fc3 A-fragment order)
#pragma unroll
    for (int mt = 0; mt < 2; mt++) {
        int mtg = wm * 2 + mt;
#pragma unroll
        for (int nf = 0; nf < 7; nf++) {
            int kg = wn * 7 + nf;
            float* base = &h2f[(mtg * 28 + kg) * 132];
#pragma unroll
            for (int i = 0; i < 4; i++) {
                int colp = 2 * t + (i & 1);           // 0..7 within n8-tile
                int col = wn * 56 + nf * 8 + colp;
                float v = acc2[mt][nf][i];
                if (col < 200) v += __ldg(&b2[col]);
                v = tf32r(fmaxf(v, 0.f));
                int lanep = g * 4 + (colp & 3);
                int comp = (i >> 1) + 2 * (colp >> 2);
                base[lanep * 4 + comp] = v;
            }
        }
    }
    CP_WAIT0();
    __syncthreads();

    // ---------------- fc3: K=224 (7 ktiles of 32), N=128 ----------------
    float acc3[2][4][4] = {};
    for (int i = 0; i < 7; i++) {
        int b = i & 1;
        if (i < 6) {
            const float* wsrc = &g_W3f[(i + 1) * 4096];
            float* wdst = &wbuf[(b ^ 1) * 4096];
            for (int j = tid; j < 1024; j += 512)
                cp16(&wdst[j * 4], &wsrc[j * 4]);
            CP_COMMIT();
        }
        const float* wbase = &wbuf[b * 4096];
#pragma unroll
        for (int k8 = 0; k8 < 4; k8++) {
            int kg = i * 4 + k8;
            float4 af0 = *(const float4*)&h2f[((wm * 2 + 0) * 28 + kg) * 132 + lane * 4];
            float4 af1 = *(const float4*)&h2f[((wm * 2 + 1) * 28 + kg) * 132 + lane * 4];
            uint32_t a00 = __float_as_uint(af0.x), a01 = __float_as_uint(af0.y);
            uint32_t a02 = __float_as_uint(af0.z), a03 = __float_as_uint(af0.w);
            uint32_t a10 = __float_as_uint(af1.x), a11 = __float_as_uint(af1.y);
            uint32_t a12 = __float_as_uint(af1.z), a13 = __float_as_uint(af1.w);
#pragma unroll
            for (int nf = 0; nf < 4; nf++) {
                float2 bf = *(const float2*)&wbase[((k8 * 16 + wn * 4 + nf) * 32 + lane) * 2];
                uint32_t b0 = __float_as_uint(bf.x), b1 = __float_as_uint(bf.y);
                mma8(acc3[0][nf], a00, a01, a02, a03, b0, b1);
                mma8(acc3[1][nf], a10, a11, a12, a13, b0, b1);
            }
        }
        if (i < 6) CP_WAIT0();
        __syncthreads();
    }

    // ---------------- fc3 epilogue + fc4 dot ----------------
    float s2[2][2] = {};
#pragma unroll
    for (int mt = 0; mt < 2; mt++) {
#pragma unroll
        for (int nf = 0; nf < 4; nf++) {
#pragma unroll
            for (int i = 0; i < 4; i++) {
                int col = wn * 32 + nf * 8 + 2 * t + (i & 1);
                float v = acc3[mt][nf][i];
                if (col < 100) v += __ldg(&b3[col]);
                v = fmaxf(v, 0.f);
                s2[mt][i >> 1] += v * sw4[col];
            }
        }
    }
#pragma unroll
    for (int mt = 0; mt < 2; mt++) {
#pragma unroll
        for (int rp = 0; rp < 2; rp++) {
            float v = s2[mt][rp];
            v += __shfl_xor_sync(0xffffffffu, v, 1);
            v += __shfl_xor_sync(0xffffffffu, v, 2);
            if (t == 0) spart[wn * 128 + wm * 32 + mt * 16 + g + 8 * rp] = v;
        }
    }
    __syncthreads();
    if (tid < TILE_E) {
        float v = spart[tid] + spart[128 + tid] + spart[256 + tid] + spart[384 + tid]
                + __ldg(&b4v[0]);
        int e = e0 + tid;
        if (e < N_EDGES) out[e] = v;
    }
}

extern "C" void kernel_launch(void* const* d_in, const int* in_sizes, int n_in,
                              void* d_out, int out_size) {
    const float* z       = (const float*)d_in[0];
    const int*   ei      = (const int*)d_in[1];
    const float* cf      = (const float*)d_in[2];
    const float* esm     = (const float*)d_in[3];
    const float* mw1     = (const float*)d_in[4];
    const float* mb1     = (const float*)d_in[5];
    const float* mw2     = (const float*)d_in[6];
    const float* mb2     = (const float*)d_in[7];
    const float* mw3     = (const float*)d_in[8];
    const float* mb3     = (const float*)d_in[9];
    const float* fc1w    = (const float*)d_in[10];
    const float* fc1b    = (const float*)d_in[11];
    const float* fc2w    = (const float*)d_in[12];
    const float* fc2b    = (const float*)d_in[13];
    const float* fc3w    = (const float*)d_in[14];
    const float* fc3b    = (const float*)d_in[15];
    const float* fc4w    = (const float*)d_in[16];
    const float* fc4b    = (const float*)d_in[17];
    float* out = (float*)d_out;

    prep_weights<<<512, 256>>>(fc1w, fc2w, fc3w);
    node_mlp<<<(N_NODES + 127) / 128, 128>>>(cf, mw1, mb1, mw2, mb2, mw3, mb3);
    build_zc<<<2048, 256>>>(z, esm);
    gemm_ab<<<dim3(13, 313), 256>>>(fc1b);

    size_t smem = (size_t)SM_WORDS * sizeof(float);   // 212992 bytes
    cudaFuncSetAttribute(edge_kernel, cudaFuncAttributeMaxDynamicSharedMemorySize, (int)smem);
    edge_kernel<<<(N_EDGES + TILE_E - 1) / TILE_E, 512, smem>>>(ei, fc2b, fc3b, fc4w, fc4b, out);
}

// round 9
// speedup vs baseline: 1.5290x; 1.5290x over previous
#include <cuda_runtime.h>
#include <cstdint>

#define N_NODES 20000
#define N_EDGES 500000

// padded dims
#define MP   20032   // node rows padded
#define K1P  416     // zc width padded (400 -> 416)
#define ABW  832     // AB row stride: A in [0,416), B in [416,832)
#define N2P  224     // fc2 out padded (200 -> 224), 28 n8-tiles
#define N3P  128     // fc3 out padded (100 -> 128), 16 n8-tiles
#define TILE_E 128

// fragment-layout table sizes
#define W2F_TOTAL (13 * 4 * 28 * 64)   // 93184 floats
#define W3F_TOTAL (7 * 4 * 16 * 64)    // 28672 floats

// ---- scratch (static device globals; allocation-free) ----
__device__ float g_M[N_NODES * 16];
__device__ __align__(16) float g_ZC[MP * K1P];
__device__ __align__(16) float g_Wcat[K1P * ABW];
__device__ __align__(16) float g_AB[MP * ABW];       // ~67 MB, L2-resident
__device__ __align__(16) float g_W2f[W2F_TOTAL];     // fc2 weights, mma-fragment order
__device__ __align__(16) float g_W3f[W3F_TOTAL];     // fc3 weights, mma-fragment order

__device__ __forceinline__ float tf32r(float x) {
    asm("cvt.rna.tf32.f32 %0, %1;" : "=f"(x) : "f"(x));
    return x;
}

__device__ __forceinline__ void mma8(float c[4],
                                     uint32_t a0, uint32_t a1, uint32_t a2, uint32_t a3,
                                     uint32_t b0, uint32_t b1) {
    asm volatile(
        "mma.sync.aligned.m16n8k8.row.col.f32.tf32.tf32.f32 "
        "{%0,%1,%2,%3}, {%4,%5,%6,%7}, {%8,%9}, {%0,%1,%2,%3};"
        : "+f"(c[0]), "+f"(c[1]), "+f"(c[2]), "+f"(c[3])
        : "r"(a0), "r"(a1), "r"(a2), "r"(a3), "r"(b0), "r"(b1));
}

__device__ __forceinline__ void cp16(void* dst_smem, const void* src_gmem) {
    uint32_t d = (uint32_t)__cvta_generic_to_shared(dst_smem);
    asm volatile("cp.async.cg.shared.global [%0], [%1], 16;\n"
                 :: "r"(d), "l"(src_gmem));
}
#define CP_COMMIT() asm volatile("cp.async.commit_group;\n" ::: "memory")
#define CP_WAIT0()  asm volatile("cp.async.wait_group 0;\n" ::: "memory")

// ---- K0: build weight tables (Wcat for gemm_ab, W2f/W3f in fragment order) ----
__global__ void prep_weights(const float* __restrict__ fc1_w,
                             const float* __restrict__ fc2_w,
                             const float* __restrict__ fc3_w) {
    const int t1 = K1P * ABW, t2 = W2F_TOTAL, t3 = W3F_TOTAL;
    for (int i = blockIdx.x * blockDim.x + threadIdx.x; i < t1 + t2 + t3;
         i += gridDim.x * blockDim.x) {
        if (i < t1) {
            int k = i / ABW, j = i % ABW;
            float v = 0.f;
            if (k < 400) {
                if (j < 400) v = fc1_w[k * 400 + j];
                else if (j >= 416 && j < 816) v = fc1_w[(400 + k) * 400 + (j - 416)];
            }
            g_Wcat[i] = tf32r(v);
        } else if (i < t1 + t2) {
            // W2f layout: ((kt*4 + k8)*28 + nf)*64 + lane*2 + p
            int ii = i - t1;
            int p = ii & 1, lane = (ii >> 1) & 31;
            int r = ii >> 6;
            int nf = r % 28, k8 = (r / 28) & 3, kt = r / 112;
            int g = lane >> 2, t = lane & 3;
            int k = kt * 32 + k8 * 8 + t + 4 * p;
            int col = nf * 8 + g;
            float v = (k < 400 && col < 200) ? fc2_w[k * 200 + col] : 0.f;
            g_W2f[ii] = tf32r(v);
        } else {
            // W3f layout: ((kt3*4 + k8)*16 + nf)*64 + lane*2 + p ; K over 224, N over 128
            int ii = i - t1 - t2;
            int p = ii & 1, lane = (ii >> 1) & 31;
            int r = ii >> 6;
            int nf = r % 16, k8 = (r / 16) & 3, kt3 = r / 64;
            int g = lane >> 2, t = lane & 3;
            int k = kt3 * 32 + k8 * 8 + t + 4 * p;
            int col = nf * 8 + g;
            float v = (k < 200 && col < 100) ? fc3_w[k * 100 + col] : 0.f;
            g_W3f[ii] = tf32r(v);
        }
    }
}

// ---- K1: tiny per-node MLP 4->64->32->16 ----
__global__ void node_mlp(const float* __restrict__ cf,
                         const float* __restrict__ w1, const float* __restrict__ b1,
                         const float* __restrict__ w2, const float* __restrict__ b2,
                         const float* __restrict__ w3, const float* __restrict__ b3) {
    __shared__ float s_w1[4 * 64], s_b1[64], s_w2[64 * 32], s_b2[32], s_w3[32 * 16], s_b3[16];
    int tid = threadIdx.x;
    for (int i = tid; i < 256; i += blockDim.x)  s_w1[i] = w1[i];
    for (int i = tid; i < 64; i += blockDim.x)   s_b1[i] = b1[i];
    for (int i = tid; i < 2048; i += blockDim.x) s_w2[i] = w2[i];
    for (int i = tid; i < 32; i += blockDim.x)   s_b2[i] = b2[i];
    for (int i = tid; i < 512; i += blockDim.x)  s_w3[i] = w3[i];
    for (int i = tid; i < 16; i += blockDim.x)   s_b3[i] = b3[i];
    __syncthreads();
    int n = blockIdx.x * blockDim.x + tid;
    if (n >= N_NODES) return;
    float c0 = cf[n * 4], c1 = cf[n * 4 + 1], c2 = cf[n * 4 + 2], c3 = cf[n * 4 + 3];
    float h1[64];
#pragma unroll
    for (int j = 0; j < 64; j++) {
        float v = s_b1[j] + c0 * s_w1[j] + c1 * s_w1[64 + j] + c2 * s_w1[128 + j] + c3 * s_w1[192 + j];
        h1[j] = fmaxf(v, 0.f);
    }
    float h2[32];
    for (int j = 0; j < 32; j++) {
        float v = s_b2[j];
        for (int k = 0; k < 64; k++) v += h1[k] * s_w2[k * 32 + j];
        h2[j] = fmaxf(v, 0.f);
    }
    for (int j = 0; j < 16; j++) {
        float v = s_b3[j];
        for (int k = 0; k < 32; k++) v += h2[k] * s_w3[k * 16 + j];
        g_M[n * 16 + j] = v;
    }
}

// ---- K2: assemble padded zc = [z | m | esm | 0], tf32-rounded ----
__global__ void build_zc(const float* __restrict__ z, const float* __restrict__ esm) {
    const int total = MP * K1P;
    for (int i = blockIdx.x * blockDim.x + threadIdx.x; i < total;
         i += gridDim.x * blockDim.x) {
        int n = i / K1P, c = i % K1P;
        float v = 0.f;
        if (n < N_NODES) {
            if (c < 64) v = z[n * 64 + c];
            else if (c < 80) v = g_M[n * 16 + c - 64];
            else if (c < 400) v = esm[n * 320 + (c - 80)];
        }
        g_ZC[i] = tf32r(v);
    }
}

// ---- K3: AB = ZC @ Wcat  (tf32 mma, BM=64 BN=64 BK=32; conflict-free strides) ----
__global__ __launch_bounds__(256) void gemm_ab(const float* __restrict__ fc1_b) {
    __shared__ float As[64 * 36];
    __shared__ float Bs[32 * 72];
    int tid = threadIdx.x;
    int w = tid >> 5, lane = tid & 31;
    int g = lane >> 2, t = lane & 3;
    int wm = w & 3, wn = w >> 2;
    int m0 = blockIdx.y * 64;
    int n0 = blockIdx.x * 64;
    float acc[4][4] = {};

    for (int kt = 0; kt < K1P; kt += 32) {
        for (int i = tid; i < 64 * 8; i += 256) {
            int r = i >> 3, c4 = (i & 7) * 4;
            float4 v = *(const float4*)&g_ZC[(m0 + r) * K1P + kt + c4];
            As[r * 36 + c4] = v.x; As[r * 36 + c4 + 1] = v.y;
            As[r * 36 + c4 + 2] = v.z; As[r * 36 + c4 + 3] = v.w;
        }
        for (int i = tid; i < 32 * 16; i += 256) {
            int r = i >> 4, c4 = (i & 15) * 4;
            float4 v = *(const float4*)&g_Wcat[(kt + r) * ABW + n0 + c4];
            Bs[r * 72 + c4] = v.x; Bs[r * 72 + c4 + 1] = v.y;
            Bs[r * 72 + c4 + 2] = v.z; Bs[r * 72 + c4 + 3] = v.w;
        }
        __syncthreads();
#pragma unroll
        for (int k8 = 0; k8 < 4; k8++) {
            int kk = k8 * 8;
            int ar = wm * 16 + g;
            uint32_t a0 = __float_as_uint(As[ar * 36 + kk + t]);
            uint32_t a1 = __float_as_uint(As[(ar + 8) * 36 + kk + t]);
            uint32_t a2 = __float_as_uint(As[ar * 36 + kk + t + 4]);
            uint32_t a3 = __float_as_uint(As[(ar + 8) * 36 + kk + t + 4]);
#pragma unroll
            for (int nf = 0; nf < 4; nf++) {
                int col = wn * 32 + nf * 8 + g;
                uint32_t b0 = __float_as_uint(Bs[(kk + t) * 72 + col]);
                uint32_t b1 = __float_as_uint(Bs[(kk + t + 4) * 72 + col]);
                mma8(acc[nf], a0, a1, a2, a3, b0, b1);
            }
        }
        __syncthreads();
    }
#pragma unroll
    for (int nf = 0; nf < 4; nf++) {
#pragma unroll
        for (int i = 0; i < 4; i++) {
            int r = m0 + wm * 16 + g + ((i >> 1) ? 8 : 0);
            int col = n0 + wn * 32 + nf * 8 + 2 * t + (i & 1);
            float v = acc[nf][i];
            if (col < 400) v += __ldg(&fc1_b[col]);   // fold b1 into A half only
            g_AB[r * ABW + col] = v;
        }
    }
}

// ============================================================================
// K4: fused edge kernel — pipelined (cp.async weights, LDG-prefetch gather,
// ONE barrier per ktile), fragment-layout smem, 4m x 4n warp tiling.
//   smem word map (FIXED: h1 buffer stride is 4224 = full tile, x2 buffers):
//     h2f   [0, 29568)        : 224 blocks of 132 (fc3 A operand, frag order)
//     h1f   [29568, 38016)    : 2 buffers x 4224  (fc2 A operand, frag order)
//     wbuf  [38016, 52352)    : 2 x 7168 (fc2 W) / 2 x 4096 (fc3 W)
//     spart [52352, 52864)    : fc4 partials [4][128]
//     sw4   [52864, 52992)    : padded w4
//     ssrc  [52992, 53120)    : src indices (int)
//     sdst  [53120, 53248)    : dst indices (int)
// ============================================================================
#define SM_H2F   0
#define SM_H1F   29568
#define H1_STRIDE 4224
#define SM_WBUF  38016
#define SM_SPART 52352
#define SM_SW4   52864
#define SM_SRC   52992
#define SM_DST   53120
#define SM_WORDS 53248

__global__ __launch_bounds__(512, 1) void edge_kernel(
    const int* __restrict__ eidx,
    const float* __restrict__ b2, const float* __restrict__ b3,
    const float* __restrict__ w4, const float* __restrict__ b4v,
    float* __restrict__ out) {
    extern __shared__ float sm[];
    float* h2f = sm + SM_H2F;
    float* h1f = sm + SM_H1F;
    float* wbuf = sm + SM_WBUF;
    float* spart = sm + SM_SPART;
    float* sw4 = sm + SM_SW4;
    int* ssrc = (int*)(sm + SM_SRC);
    int* sdst = (int*)(sm + SM_DST);

    int tid = threadIdx.x;
    int w = tid >> 5, lane = tid & 31;
    int g = lane >> 2, t = lane & 3;
    int wm = w & 3, wn = w >> 2;   // 4 m-warps (32 rows each) x 4 n-warps
    int e0 = blockIdx.x * TILE_E;

    if (tid < TILE_E) {
        int e = e0 + tid;
        int s = 0, d = 0;
        if (e < N_EDGES) { s = eidx[e]; d = eidx[N_EDGES + e]; }
        s = min(max(s, 0), N_NODES - 1);
        d = min(max(d, 0), N_NODES - 1);
        ssrc[tid] = s; sdst[tid] = d;
        sw4[tid] = (tid < 100) ? __ldg(&w4[tid]) : 0.f;
    }
    __syncthreads();

    // gather-thread geometry: each thread owns (edge ge, k8 slice k8g)
    int ge = tid >> 2;
    int k8g = tid & 3;
    int gg = ge & 7, rpg = (ge >> 3) & 1, mtg_g = ge >> 4;
    int h1off = (mtg_g * 4 + k8g) * 132 + gg * 16 + rpg;
    const float* srowp = &g_AB[(size_t)ssrc[ge] * ABW];
    const float* drowp = &g_AB[(size_t)sdst[ge] * ABW + 416];
    int q = k8g * 8;

    float acc2[2][7][4] = {};

    // -------- prologue: stage tile 0 (gather + weights) --------
    {
        float4 a0 = *(const float4*)&srowp[q];
        float4 a1 = *(const float4*)&srowp[q + 4];
        float4 c0 = *(const float4*)&drowp[q];
        float4 c1 = *(const float4*)&drowp[q + 4];
        for (int j = tid; j < 1792; j += 512)
            cp16(&wbuf[j * 4], &g_W2f[j * 4]);
        CP_COMMIT();
        float* hw = &h1f[h1off];
        hw[0]  = tf32r(fmaxf(a0.x + c0.x, 0.f));
        hw[4]  = tf32r(fmaxf(a0.y + c0.y, 0.f));
        hw[8]  = tf32r(fmaxf(a0.z + c0.z, 0.f));
        hw[12] = tf32r(fmaxf(a0.w + c0.w, 0.f));
        hw[2]  = tf32r(fmaxf(a1.x + c1.x, 0.f));
        hw[6]  = tf32r(fmaxf(a1.y + c1.y, 0.f));
        hw[10] = tf32r(fmaxf(a1.z + c1.z, 0.f));
        hw[14] = tf32r(fmaxf(a1.w + c1.w, 0.f));
        CP_WAIT0();
    }
    __syncthreads();

    // ---------------- fc2: K=416 (13 ktiles of 32), N=224 ----------------
    for (int i = 0; i < 13; i++) {
        int b = i & 1;
        float4 a0, a1, c0, c1;
        if (i < 12) {   // prefetch tile i+1: gather -> regs, weights -> alt buffer
            int kt = (i + 1) * 32;
            a0 = *(const float4*)&srowp[kt + q];
            a1 = *(const float4*)&srowp[kt + q + 4];
            c0 = *(const float4*)&drowp[kt + q];
            c1 = *(const float4*)&drowp[kt + q + 4];
            const float* wsrc = &g_W2f[(i + 1) * 7168];
            float* wdst = &wbuf[(b ^ 1) * 7168];
            for (int j = tid; j < 1792; j += 512)
                cp16(&wdst[j * 4], &wsrc[j * 4]);
            CP_COMMIT();
        }
        const float* hbase = &h1f[b * H1_STRIDE];
        const float* wbase = &wbuf[b * 7168];
#pragma unroll
        for (int k8 = 0; k8 < 4; k8++) {
            float4 af0 = *(const float4*)&hbase[((wm * 2 + 0) * 4 + k8) * 132 + lane * 4];
            float4 af1 = *(const float4*)&hbase[((wm * 2 + 1) * 4 + k8) * 132 + lane * 4];
            uint32_t a00 = __float_as_uint(af0.x), a01 = __float_as_uint(af0.y);
            uint32_t a02 = __float_as_uint(af0.z), a03 = __float_as_uint(af0.w);
            uint32_t a10 = __float_as_uint(af1.x), a11 = __float_as_uint(af1.y);
            uint32_t a12 = __float_as_uint(af1.z), a13 = __float_as_uint(af1.w);
#pragma unroll
            for (int nf = 0; nf < 7; nf++) {
                float2 bf = *(const float2*)&wbase[((k8 * 28 + wn * 7 + nf) * 32 + lane) * 2];
                uint32_t b0 = __float_as_uint(bf.x), b1 = __float_as_uint(bf.y);
                mma8(acc2[0][nf], a00, a01, a02, a03, b0, b1);
                mma8(acc2[1][nf], a10, a11, a12, a13, b0, b1);
            }
        }
        if (i < 12) {   // commit prefetched gather into alt h1 buffer
            float* hw = &h1f[(b ^ 1) * H1_STRIDE + h1off];
            hw[0]  = tf32r(fmaxf(a0.x + c0.x, 0.f));
            hw[4]  = tf32r(fmaxf(a0.y + c0.y, 0.f));
            hw[8]  = tf32r(fmaxf(a0.z + c0.z, 0.f));
            hw[12] = tf32r(fmaxf(a0.w + c0.w, 0.f));
            hw[2]  = tf32r(fmaxf(a1.x + c1.x, 0.f));
            hw[6]  = tf32r(fmaxf(a1.y + c1.y, 0.f));
            hw[10] = tf32r(fmaxf(a1.z + c1.z, 0.f));
            hw[14] = tf32r(fmaxf(a1.w + c1.w, 0.f));
            CP_WAIT0();
        }
        __syncthreads();
    }

    // prefetch fc3 weights tile 0 (overlaps epilogue scatter below)
    for (int j = tid; j < 1024; j += 512)
        cp16(&wbuf[j * 4], &g_W3f[j * 4]);
    CP_COMMIT();

    // fc2 epilogue: bias + relu + tf32-round, scatter into h2f (fc3 A-fragment order)
#pragma unroll
    for (int mt = 0; mt < 2; mt++) {
        int mtg = wm * 2 + mt;
#pragma unroll
        for (int nf = 0; nf < 7; nf++) {
            int kg = wn * 7 + nf;
            float* base = &h2f[(mtg * 28 + kg) * 132];
#pragma unroll
            for (int i = 0; i < 4; i++) {
                int colp = 2 * t + (i & 1);           // 0..7 within n8-tile
                int col = wn * 56 + nf * 8 + colp;
                float v = acc2[mt][nf][i];
                if (col < 200) v += __ldg(&b2[col]);
                v = tf32r(fmaxf(v, 0.f));
                int lanep = g * 4 + (colp & 3);
                int comp = (i >> 1) + 2 * (colp >> 2);
                base[lanep * 4 + comp] = v;
            }
        }
    }
    CP_WAIT0();
    __syncthreads();

    // ---------------- fc3: K=224 (7 ktiles of 32), N=128 ----------------
    float acc3[2][4][4] = {};
    for (int i = 0; i < 7; i++) {
        int b = i & 1;
        if (i < 6) {
            const float* wsrc = &g_W3f[(i + 1) * 4096];
            float* wdst = &wbuf[(b ^ 1) * 4096];
            for (int j = tid; j < 1024; j += 512)
                cp16(&wdst[j * 4], &wsrc[j * 4]);
            CP_COMMIT();
        }
        const float* wbase = &wbuf[b * 4096];
#pragma unroll
        for (int k8 = 0; k8 < 4; k8++) {
            int kg = i * 4 + k8;
            float4 af0 = *(const float4*)&h2f[((wm * 2 + 0) * 28 + kg) * 132 + lane * 4];
            float4 af1 = *(const float4*)&h2f[((wm * 2 + 1) * 28 + kg) * 132 + lane * 4];
            uint32_t a00 = __float_as_uint(af0.x), a01 = __float_as_uint(af0.y);
            uint32_t a02 = __float_as_uint(af0.z), a03 = __float_as_uint(af0.w);
            uint32_t a10 = __float_as_uint(af1.x), a11 = __float_as_uint(af1.y);
            uint32_t a12 = __float_as_uint(af1.z), a13 = __float_as_uint(af1.w);
#pragma unroll
            for (int nf = 0; nf < 4; nf++) {
                float2 bf = *(const float2*)&wbase[((k8 * 16 + wn * 4 + nf) * 32 + lane) * 2];
                uint32_t b0 = __float_as_uint(bf.x), b1 = __float_as_uint(bf.y);
                mma8(acc3[0][nf], a00, a01, a02, a03, b0, b1);
                mma8(acc3[1][nf], a10, a11, a12, a13, b0, b1);
            }
        }
        if (i < 6) CP_WAIT0();
        __syncthreads();
    }

    // ---------------- fc3 epilogue + fc4 dot ----------------
    float s2[2][2] = {};
#pragma unroll
    for (int mt = 0; mt < 2; mt++) {
#pragma unroll
        for (int nf = 0; nf < 4; nf++) {
#pragma unroll
            for (int i = 0; i < 4; i++) {
                int col = wn * 32 + nf * 8 + 2 * t + (i & 1);
                float v = acc3[mt][nf][i];
                if (col < 100) v += __ldg(&b3[col]);
                v = fmaxf(v, 0.f);
                s2[mt][i >> 1] += v * sw4[col];
            }
        }
    }
#pragma unroll
    for (int mt = 0; mt < 2; mt++) {
#pragma unroll
        for (int rp = 0; rp < 2; rp++) {
            float v = s2[mt][rp];
            v += __shfl_xor_sync(0xffffffffu, v, 1);
            v += __shfl_xor_sync(0xffffffffu, v, 2);
            if (t == 0) spart[wn * 128 + wm * 32 + mt * 16 + g + 8 * rp] = v;
        }
    }
    __syncthreads();
    if (tid < TILE_E) {
        float v = spart[tid] + spart[128 + tid] + spart[256 + tid] + spart[384 + tid]
                + __ldg(&b4v[0]);
        int e = e0 + tid;
        if (e < N_EDGES) out[e] = v;
    }
}

extern "C" void kernel_launch(void* const* d_in, const int* in_sizes, int n_in,
                              void* d_out, int out_size) {
    const float* z       = (const float*)d_in[0];
    const int*   ei      = (const int*)d_in[1];
    const float* cf      = (const float*)d_in[2];
    const float* esm     = (const float*)d_in[3];
    const float* mw1     = (const float*)d_in[4];
    const float* mb1     = (const float*)d_in[5];
    const float* mw2     = (const float*)d_in[6];
    const float* mb2     = (const float*)d_in[7];
    const float* mw3     = (const float*)d_in[8];
    const float* mb3     = (const float*)d_in[9];
    const float* fc1w    = (const float*)d_in[10];
    const float* fc1b    = (const float*)d_in[11];
    const float* fc2w    = (const float*)d_in[12];
    const float* fc2b    = (const float*)d_in[13];
    const float* fc3w    = (const float*)d_in[14];
    const float* fc3b    = (const float*)d_in[15];
    const float* fc4w    = (const float*)d_in[16];
    const float* fc4b    = (const float*)d_in[17];
    float* out = (float*)d_out;

    prep_weights<<<512, 256>>>(fc1w, fc2w, fc3w);
    node_mlp<<<(N_NODES + 127) / 128, 128>>>(cf, mw1, mb1, mw2, mb2, mw3, mb3);
    build_zc<<<2048, 256>>>(z, esm);
    gemm_ab<<<dim3(13, 313), 256>>>(fc1b);

    size_t smem = (size_t)SM_WORDS * sizeof(float);   // 212992 bytes
    cudaFuncSetAttribute(edge_kernel, cudaFuncAttributeMaxDynamicSharedMemorySize, (int)smem);
    edge_kernel<<<(N_EDGES + TILE_E - 1) / TILE_E, 512, smem>>>(ei, fc2b, fc3b, fc4w, fc4b, out);
}

// round 11
// speedup vs baseline: 1.6359x; 1.0699x over previous
#include <cuda_runtime.h>
#include <cstdint>

#define N_NODES 20000
#define N_EDGES 500000

#define MP   20032
#define K1P  416
#define ABW  832
#define TILE_E 128

// fragment tables: fc2 = 13 kchunks x (4 k8 x 25 tiles x 64), fc3 = 25 k8 x 13 tiles x 64
#define W2F_TOTAL (13 * 6400)   // 83200 floats
#define W3F_TOTAL (25 * 13 * 64) // 20800 floats

__device__ float g_M[N_NODES * 16];
__device__ __align__(16) float g_ZC[MP * K1P];
__device__ __align__(16) float g_Wcat[K1P * ABW];
__device__ __align__(16) float g_AB[MP * ABW];       // ~67 MB, L2-resident
__device__ __align__(16) float g_W2f[W2F_TOTAL];
__device__ __align__(16) float g_W3f[W3F_TOTAL];

__device__ __forceinline__ float tf32r(float x) {
    asm("cvt.rna.tf32.f32 %0, %1;" : "=f"(x) : "f"(x));
    return x;
}

__device__ __forceinline__ void mma8(float c[4],
                                     uint32_t a0, uint32_t a1, uint32_t a2, uint32_t a3,
                                     uint32_t b0, uint32_t b1) {
    asm volatile(
        "mma.sync.aligned.m16n8k8.row.col.f32.tf32.tf32.f32 "
        "{%0,%1,%2,%3}, {%4,%5,%6,%7}, {%8,%9}, {%0,%1,%2,%3};"
        : "+f"(c[0]), "+f"(c[1]), "+f"(c[2]), "+f"(c[3])
        : "r"(a0), "r"(a1), "r"(a2), "r"(a3), "r"(b0), "r"(b1));
}

__device__ __forceinline__ void cp16(void* dst_smem, const void* src_gmem) {
    uint32_t d = (uint32_t)__cvta_generic_to_shared(dst_smem);
    asm volatile("cp.async.cg.shared.global [%0], [%1], 16;\n"
                 :: "r"(d), "l"(src_gmem));
}
#define CP_COMMIT() asm volatile("cp.async.commit_group;\n" ::: "memory")
#define CP_WAIT0()  asm volatile("cp.async.wait_group 0;\n" ::: "memory")

// ---- K0: weight tables. W2f: ((kt*4+k8)*25 + gtile)*64 + lane*2 + p
//                         W3f: ((k8g)*13 + gtile)*64 + lane*2 + p
__global__ void prep_weights(const float* __restrict__ fc1_w,
                             const float* __restrict__ fc2_w,
                             const float* __restrict__ fc3_w) {
    const int t1 = K1P * ABW, t2 = W2F_TOTAL, t3 = W3F_TOTAL;
    for (int i = blockIdx.x * blockDim.x + threadIdx.x; i < t1 + t2 + t3;
         i += gridDim.x * blockDim.x) {
        if (i < t1) {
            int k = i / ABW, j = i % ABW;
            float v = 0.f;
            if (k < 400) {
                if (j < 400) v = fc1_w[k * 400 + j];
                else if (j >= 416 && j < 816) v = fc1_w[(400 + k) * 400 + (j - 416)];
            }
            g_Wcat[i] = tf32r(v);
        } else if (i < t1 + t2) {
            int ii = i - t1;
            int p = ii & 1, lane = (ii >> 1) & 31;
            int r = ii >> 6;
            int gtile = r % 25, k8 = (r / 25) & 3, kt = r / 100;
            int g = lane >> 2, t = lane & 3;
            int k = kt * 32 + k8 * 8 + t + 4 * p;      // 0..415
            int col = gtile * 8 + g;                    // 0..199, all real
            g_W2f[ii] = tf32r((k < 400) ? fc2_w[k * 200 + col] : 0.f);
        } else {
            int ii = i - t1 - t2;
            int p = ii & 1, lane = (ii >> 1) & 31;
            int r = ii >> 6;
            int gtile = r % 13, k8g = r / 13;           // k8g 0..24
            int g = lane >> 2, t = lane & 3;
            int k = k8g * 8 + t + 4 * p;                // 0..199, all real
            int col = gtile * 8 + g;                    // 0..103
            g_W3f[ii] = tf32r((col < 100) ? fc3_w[k * 100 + col] : 0.f);
        }
    }
}

// ---- K1: tiny per-node MLP 4->64->32->16 ----
__global__ void node_mlp(const float* __restrict__ cf,
                         const float* __restrict__ w1, const float* __restrict__ b1,
                         const float* __restrict__ w2, const float* __restrict__ b2,
                         const float* __restrict__ w3, const float* __restrict__ b3) {
    __shared__ float s_w1[256], s_b1[64], s_w2[2048], s_b2[32], s_w3[512], s_b3[16];
    int tid = threadIdx.x;
    for (int i = tid; i < 256; i += blockDim.x)  s_w1[i] = w1[i];
    for (int i = tid; i < 64; i += blockDim.x)   s_b1[i] = b1[i];
    for (int i = tid; i < 2048; i += blockDim.x) s_w2[i] = w2[i];
    for (int i = tid; i < 32; i += blockDim.x)   s_b2[i] = b2[i];
    for (int i = tid; i < 512; i += blockDim.x)  s_w3[i] = w3[i];
    for (int i = tid; i < 16; i += blockDim.x)   s_b3[i] = b3[i];
    __syncthreads();
    int n = blockIdx.x * blockDim.x + tid;
    if (n >= N_NODES) return;
    float c0 = cf[n * 4], c1 = cf[n * 4 + 1], c2 = cf[n * 4 + 2], c3 = cf[n * 4 + 3];
    float h1[64];
#pragma unroll
    for (int j = 0; j < 64; j++)
        h1[j] = fmaxf(s_b1[j] + c0 * s_w1[j] + c1 * s_w1[64 + j] + c2 * s_w1[128 + j] + c3 * s_w1[192 + j], 0.f);
    float h2[32];
    for (int j = 0; j < 32; j++) {
        float v = s_b2[j];
        for (int k = 0; k < 64; k++) v += h1[k] * s_w2[k * 32 + j];
        h2[j] = fmaxf(v, 0.f);
    }
    for (int j = 0; j < 16; j++) {
        float v = s_b3[j];
        for (int k = 0; k < 32; k++) v += h2[k] * s_w3[k * 16 + j];
        g_M[n * 16 + j] = v;
    }
}

// ---- K2: assemble padded zc ----
__global__ void build_zc(const float* __restrict__ z, const float* __restrict__ esm) {
    const int total = MP * K1P;
    for (int i = blockIdx.x * blockDim.x + threadIdx.x; i < total;
         i += gridDim.x * blockDim.x) {
        int n = i / K1P, c = i % K1P;
        float v = 0.f;
        if (n < N_NODES) {
            if (c < 64) v = z[n * 64 + c];
            else if (c < 80) v = g_M[n * 16 + c - 64];
            else if (c < 400) v = esm[n * 320 + (c - 80)];
        }
        g_ZC[i] = tf32r(v);
    }
}

// ---- K3: AB = ZC @ Wcat (unchanged from R9 WIN) ----
__global__ __launch_bounds__(256) void gemm_ab(const float* __restrict__ fc1_b) {
    __shared__ float As[64 * 36];
    __shared__ float Bs[32 * 72];
    int tid = threadIdx.x;
    int w = tid >> 5, lane = tid & 31;
    int g = lane >> 2, t = lane & 3;
    int wm = w & 3, wn = w >> 2;
    int m0 = blockIdx.y * 64, n0 = blockIdx.x * 64;
    float acc[4][4] = {};
    for (int kt = 0; kt < K1P; kt += 32) {
        for (int i = tid; i < 64 * 8; i += 256) {
            int r = i >> 3, c4 = (i & 7) * 4;
            float4 v = *(const float4*)&g_ZC[(m0 + r) * K1P + kt + c4];
            As[r * 36 + c4] = v.x; As[r * 36 + c4 + 1] = v.y;
            As[r * 36 + c4 + 2] = v.z; As[r * 36 + c4 + 3] = v.w;
        }
        for (int i = tid; i < 32 * 16; i += 256) {
            int r = i >> 4, c4 = (i & 15) * 4;
            float4 v = *(const float4*)&g_Wcat[(kt + r) * ABW + n0 + c4];
            Bs[r * 72 + c4] = v.x; Bs[r * 72 + c4 + 1] = v.y;
            Bs[r * 72 + c4 + 2] = v.z; Bs[r * 72 + c4 + 3] = v.w;
        }
        __syncthreads();
#pragma unroll
        for (int k8 = 0; k8 < 4; k8++) {
            int kk = k8 * 8, ar = wm * 16 + g;
            uint32_t a0 = __float_as_uint(As[ar * 36 + kk + t]);
            uint32_t a1 = __float_as_uint(As[(ar + 8) * 36 + kk + t]);
            uint32_t a2 = __float_as_uint(As[ar * 36 + kk + t + 4]);
            uint32_t a3 = __float_as_uint(As[(ar + 8) * 36 + kk + t + 4]);
#pragma unroll
            for (int nf = 0; nf < 4; nf++) {
                int col = wn * 32 + nf * 8 + g;
                uint32_t b0 = __float_as_uint(Bs[(kk + t) * 72 + col]);
                uint32_t b1 = __float_as_uint(Bs[(kk + t + 4) * 72 + col]);
                mma8(acc[nf], a0, a1, a2, a3, b0, b1);
            }
        }
        __syncthreads();
    }
#pragma unroll
    for (int nf = 0; nf < 4; nf++)
#pragma unroll
        for (int i = 0; i < 4; i++) {
            int r = m0 + wm * 16 + g + ((i >> 1) ? 8 : 0);
            int col = n0 + wn * 32 + nf * 8 + 2 * t + (i & 1);
            float v = acc[nf][i];
            if (col < 400) v += __ldg(&fc1_b[col]);
            g_AB[r * ABW + col] = v;
        }
}

// ============================================================================
// K4: fused edge kernel — R9 pipeline, padding-free tiling.
//   fc2: N=200 exact, 25 n8-tiles, warp split {7,6,6,6}
//   fc3: K=200 exact (25 k8, 5 chunks of 5), N=104, 13 tiles, split {4,3,3,3}
//   smem word map:
//     h2f   [0, 26400)        : 8 mtg x 25 kg x 132
//     h1f   [26400, 34848)    : 2 x 4224
//     wbuf  [34848, 47648)    : 2 x 6400 (fc2) / 2 x 4160 (fc3)
//     spart [47648, 48160)  sw4 [48160, 48288)  src [48288,48416)  dst [48416,48544)
// ============================================================================
#define SM_H2F   0
#define SM_H1F   26400
#define H1_STRIDE 4224
#define SM_WBUF  34848
#define SM_SPART 47648
#define SM_SW4   48160
#define SM_SRC   48288
#define SM_DST   48416
#define SM_WORDS 48544

__global__ __launch_bounds__(512, 1) void edge_kernel(
    const int* __restrict__ eidx,
    const float* __restrict__ b2, const float* __restrict__ b3,
    const float* __restrict__ w4, const float* __restrict__ b4v,
    float* __restrict__ out) {
    extern __shared__ float sm[];
    float* h2f = sm + SM_H2F;
    float* h1f = sm + SM_H1F;
    float* wbuf = sm + SM_WBUF;
    float* spart = sm + SM_SPART;
    float* sw4 = sm + SM_SW4;
    int* ssrc = (int*)(sm + SM_SRC);
    int* sdst = (int*)(sm + SM_DST);

    int tid = threadIdx.x;
    int w = tid >> 5, lane = tid & 31;
    int g = lane >> 2, t = lane & 3;
    int wm = w & 3, wn = w >> 2;
    // uneven n-tile assignment
    int gb2 = (wn == 0) ? 0 : (7 + (wn - 1) * 6);   // {0,7,13,19}
    int nfc2 = (wn == 0) ? 7 : 6;
    int cb2 = gb2 * 8;                               // {0,56,104,152}
    int gb3 = (wn == 0) ? 0 : (4 + (wn - 1) * 3);   // {0,4,7,10}
    int nfc3 = (wn == 0) ? 4 : 3;
    int cb3 = gb3 * 8;                               // {0,32,56,80}
    int e0 = blockIdx.x * TILE_E;

    if (tid < TILE_E) {
        int e = e0 + tid, s = 0, d = 0;
        if (e < N_EDGES) { s = eidx[e]; d = eidx[N_EDGES + e]; }
        s = min(max(s, 0), N_NODES - 1);
        d = min(max(d, 0), N_NODES - 1);
        ssrc[tid] = s; sdst[tid] = d;
        sw4[tid] = (tid < 100) ? __ldg(&w4[tid]) : 0.f;
    }
    __syncthreads();

    int ge = tid >> 2;
    int k8g = tid & 3;
    int gg = ge & 7, rpg = (ge >> 3) & 1, mtg_g = ge >> 4;
    int h1off = (mtg_g * 4 + k8g) * 132 + gg * 16 + rpg;
    const float* srowp = &g_AB[(size_t)ssrc[ge] * ABW];
    const float* drowp = &g_AB[(size_t)sdst[ge] * ABW + 416];
    int q = k8g * 8;

    float acc2[2][7][4] = {};

    // -------- prologue: stage fc2 tile 0 --------
    {
        float4 a0 = *(const float4*)&srowp[q];
        float4 a1 = *(const float4*)&srowp[q + 4];
        float4 c0 = *(const float4*)&drowp[q];
        float4 c1 = *(const float4*)&drowp[q + 4];
        for (int j = tid; j < 1600; j += 512)
            cp16(&wbuf[j * 4], &g_W2f[j * 4]);
        CP_COMMIT();
        float* hw = &h1f[h1off];
        hw[0]  = tf32r(fmaxf(a0.x + c0.x, 0.f));
        hw[4]  = tf32r(fmaxf(a0.y + c0.y, 0.f));
        hw[8]  = tf32r(fmaxf(a0.z + c0.z, 0.f));
        hw[12] = tf32r(fmaxf(a0.w + c0.w, 0.f));
        hw[2]  = tf32r(fmaxf(a1.x + c1.x, 0.f));
        hw[6]  = tf32r(fmaxf(a1.y + c1.y, 0.f));
        hw[10] = tf32r(fmaxf(a1.z + c1.z, 0.f));
        hw[14] = tf32r(fmaxf(a1.w + c1.w, 0.f));
        CP_WAIT0();
    }
    __syncthreads();

    // ---------------- fc2: K=416 (13 ktiles), N=200 (25 tiles) ----------------
    for (int i = 0; i < 13; i++) {
        int b = i & 1;
        float4 a0, a1, c0, c1;
        if (i < 12) {
            int kt = (i + 1) * 32;
            a0 = *(const float4*)&srowp[kt + q];
            a1 = *(const float4*)&srowp[kt + q + 4];
            c0 = *(const float4*)&drowp[kt + q];
            c1 = *(const float4*)&drowp[kt + q + 4];
            const float* wsrc = &g_W2f[(i + 1) * 6400];
            float* wdst = &wbuf[(b ^ 1) * 6400];
            for (int j = tid; j < 1600; j += 512)
                cp16(&wdst[j * 4], &wsrc[j * 4]);
            CP_COMMIT();
        }
        const float* hbase = &h1f[b * H1_STRIDE];
        const float* wbase = &wbuf[b * 6400];
#pragma unroll
        for (int k8 = 0; k8 < 4; k8++) {
            float4 af0 = *(const float4*)&hbase[((wm * 2 + 0) * 4 + k8) * 132 + lane * 4];
            float4 af1 = *(const float4*)&hbase[((wm * 2 + 1) * 4 + k8) * 132 + lane * 4];
            uint32_t a00 = __float_as_uint(af0.x), a01 = __float_as_uint(af0.y);
            uint32_t a02 = __float_as_uint(af0.z), a03 = __float_as_uint(af0.w);
            uint32_t a10 = __float_as_uint(af1.x), a11 = __float_as_uint(af1.y);
            uint32_t a12 = __float_as_uint(af1.z), a13 = __float_as_uint(af1.w);
#pragma unroll
            for (int nf = 0; nf < 7; nf++) {
                if (nf < nfc2) {
                    float2 bf = *(const float2*)&wbase[((k8 * 25 + gb2 + nf) * 32 + lane) * 2];
                    uint32_t b0 = __float_as_uint(bf.x), b1 = __float_as_uint(bf.y);
                    mma8(acc2[0][nf], a00, a01, a02, a03, b0, b1);
                    mma8(acc2[1][nf], a10, a11, a12, a13, b0, b1);
                }
            }
        }
        if (i < 12) {
            float* hw = &h1f[(b ^ 1) * H1_STRIDE + h1off];
            hw[0]  = tf32r(fmaxf(a0.x + c0.x, 0.f));
            hw[4]  = tf32r(fmaxf(a0.y + c0.y, 0.f));
            hw[8]  = tf32r(fmaxf(a0.z + c0.z, 0.f));
            hw[12] = tf32r(fmaxf(a0.w + c0.w, 0.f));
            hw[2]  = tf32r(fmaxf(a1.x + c1.x, 0.f));
            hw[6]  = tf32r(fmaxf(a1.y + c1.y, 0.f));
            hw[10] = tf32r(fmaxf(a1.z + c1.z, 0.f));
            hw[14] = tf32r(fmaxf(a1.w + c1.w, 0.f));
            CP_WAIT0();
        }
        __syncthreads();
    }

    // prefetch fc3 weight chunk 0 (k8g 0..4), overlaps the epilogue scatter
    for (int j = tid; j < 1040; j += 512)
        cp16(&wbuf[j * 4], &g_W3f[j * 4]);
    CP_COMMIT();

    // fc2 epilogue: bias + relu + tf32-round -> h2f (fc3 A-fragment order, 25 kg)
#pragma unroll
    for (int mt = 0; mt < 2; mt++) {
        int mtg = wm * 2 + mt;
#pragma unroll
        for (int nf = 0; nf < 7; nf++) {
            if (nf < nfc2) {
                int kg = gb2 + nf;
                float* base = &h2f[(mtg * 25 + kg) * 132];
#pragma unroll
                for (int i = 0; i < 4; i++) {
                    int colp = 2 * t + (i & 1);
                    int col = cb2 + nf * 8 + colp;       // always < 200
                    float v = acc2[mt][nf][i] + __ldg(&b2[col]);
                    v = tf32r(fmaxf(v, 0.f));
                    int lanep = g * 4 + (colp & 3);
                    int comp = (i >> 1) + 2 * (colp >> 2);
                    base[lanep * 4 + comp] = v;
                }
            }
        }
    }
    CP_WAIT0();
    __syncthreads();

    // ---------------- fc3: K=200 (25 k8, 5 chunks of 5), N=104 (13 tiles) ----------------
    float acc3[2][4][4] = {};
    for (int i = 0; i < 5; i++) {
        int b = i & 1;
        if (i < 4) {
            const float* wsrc = &g_W3f[(i + 1) * 4160];
            float* wdst = &wbuf[(b ^ 1) * 4160];
            for (int j = tid; j < 1040; j += 512)
                cp16(&wdst[j * 4], &wsrc[j * 4]);
            CP_COMMIT();
        }
        const float* wbase = &wbuf[b * 4160];
#pragma unroll
        for (int k8 = 0; k8 < 5; k8++) {
            int kg = i * 5 + k8;
            float4 af0 = *(const float4*)&h2f[((wm * 2 + 0) * 25 + kg) * 132 + lane * 4];
            float4 af1 = *(const float4*)&h2f[((wm * 2 + 1) * 25 + kg) * 132 + lane * 4];
            uint32_t a00 = __float_as_uint(af0.x), a01 = __float_as_uint(af0.y);
            uint32_t a02 = __float_as_uint(af0.z), a03 = __float_as_uint(af0.w);
            uint32_t a10 = __float_as_uint(af1.x), a11 = __float_as_uint(af1.y);
            uint32_t a12 = __float_as_uint(af1.z), a13 = __float_as_uint(af1.w);
#pragma unroll
            for (int nf = 0; nf < 4; nf++) {
                if (nf < nfc3) {
                    float2 bf = *(const float2*)&wbase[((k8 * 13 + gb3 + nf) * 32 + lane) * 2];
                    uint32_t b0 = __float_as_uint(bf.x), b1 = __float_as_uint(bf.y);
                    mma8(acc3[0][nf], a00, a01, a02, a03, b0, b1);
                    mma8(acc3[1][nf], a10, a11, a12, a13, b0, b1);
                }
            }
        }
        if (i < 4) CP_WAIT0();
        __syncthreads();
    }

    // ---------------- fc3 epilogue + fc4 dot ----------------
    float s2[2][2] = {};
#pragma unroll
    for (int mt = 0; mt < 2; mt++) {
#pragma unroll
        for (int nf = 0; nf < 4; nf++) {
            if (nf < nfc3) {
#pragma unroll
                for (int i = 0; i < 4; i++) {
                    int col = cb3 + nf * 8 + 2 * t + (i & 1);   // 0..103
                    float v = acc3[mt][nf][i];
                    if (col < 100) v += __ldg(&b3[col]);
                    v = fmaxf(v, 0.f);
                    s2[mt][i >> 1] += v * sw4[col];             // sw4 zero-padded
                }
            }
        }
    }
#pragma unroll
    for (int mt = 0; mt < 2; mt++) {
#pragma unroll
        for (int rp = 0; rp < 2; rp++) {
            float v = s2[mt][rp];
            v += __shfl_xor_sync(0xffffffffu, v, 1);
            v += __shfl_xor_sync(0xffffffffu, v, 2);
            if (t == 0) spart[wn * 128 + wm * 32 + mt * 16 + g + 8 * rp] = v;
        }
    }
    __syncthreads();
    if (tid < TILE_E) {
        float v = spart[tid] + spart[128 + tid] + spart[256 + tid] + spart[384 + tid]
                + __ldg(&b4v[0]);
        int e = e0 + tid;
        if (e < N_EDGES) out[e] = v;
    }
}

extern "C" void kernel_launch(void* const* d_in, const int* in_sizes, int n_in,
                              void* d_out, int out_size) {
    const float* z    = (const float*)d_in[0];
    const int*   ei   = (const int*)d_in[1];
    const float* cf   = (const float*)d_in[2];
    const float* esm  = (const float*)d_in[3];
    const float* mw1  = (const float*)d_in[4];
    const float* mb1  = (const float*)d_in[5];
    const float* mw2  = (const float*)d_in[6];
    const float* mb2  = (const float*)d_in[7];
    const float* mw3  = (const float*)d_in[8];
    const float* mb3  = (const float*)d_in[9];
    const float* fc1w = (const float*)d_in[10];
    const float* fc1b = (const float*)d_in[11];
    const float* fc2w = (const float*)d_in[12];
    const float* fc2b = (const float*)d_in[13];
    const float* fc3w = (const float*)d_in[14];
    const float* fc3b = (const float*)d_in[15];
    const float* fc4w = (const float*)d_in[16];
    const float* fc4b = (const float*)d_in[17];
    float* out = (float*)d_out;

    prep_weights<<<512, 256>>>(fc1w, fc2w, fc3w);
    node_mlp<<<(N_NODES + 127) / 128, 128>>>(cf, mw1, mb1, mw2, mb2, mw3, mb3);
    build_zc<<<2048, 256>>>(z, esm);
    gemm_ab<<<dim3(13, 313), 256>>>(fc1b);

    size_t smem = (size_t)SM_WORDS * sizeof(float);   // 194176 bytes
    cudaFuncSetAttribute(edge_kernel, cudaFuncAttributeMaxDynamicSharedMemorySize, (int)smem);
    edge_kernel<<<(N_EDGES + TILE_E - 1) / TILE_E, 512, smem>>>(ei, fc2b, fc3b, fc4w, fc4b, out);
}

// round 12
// speedup vs baseline: 2.3253x; 1.4214x over previous
#include <cuda_runtime.h>
#include <cuda_fp16.h>
#include <cstdint>

#define N_NODES 20000
#define N_EDGES 500000

#define MP   20032
#define K1P  416
#define ABW  832
#define TILE_E 128

// fp16 fragment tables
#define W2H_TOTAL (13 * 3200)        // 13 k32 chunks x (2 ks x 25 tiles x 64 words)
#define W3H_TOTAL (13 * 13 * 64)     // 13 ks x 13 tiles x 64 words = 10816

__device__ float g_M[N_NODES * 16];
__device__ __align__(16) float g_ZC[MP * K1P];
__device__ __align__(16) float g_Wcat[K1P * ABW];
__device__ __align__(16) float g_AB[MP * ABW];          // ~67 MB, L2-resident
__device__ __align__(16) uint32_t g_W2h[W2H_TOTAL];     // fc2 W, fp16 B-fragment order
__device__ __align__(16) uint32_t g_W3h[W3H_TOTAL];     // fc3 W, fp16 B-fragment order

__device__ __forceinline__ float tf32r(float x) {
    asm("cvt.rna.tf32.f32 %0, %1;" : "=f"(x) : "f"(x));
    return x;
}
__device__ __forceinline__ uint32_t pack2(float lo, float hi) {
    __half2 h = __floats2half2_rn(lo, hi);
    return *(uint32_t*)&h;
}

// tf32 m16n8k8 (gemm_ab only)
__device__ __forceinline__ void mma8(float c[4],
                                     uint32_t a0, uint32_t a1, uint32_t a2, uint32_t a3,
                                     uint32_t b0, uint32_t b1) {
    asm volatile(
        "mma.sync.aligned.m16n8k8.row.col.f32.tf32.tf32.f32 "
        "{%0,%1,%2,%3}, {%4,%5,%6,%7}, {%8,%9}, {%0,%1,%2,%3};"
        : "+f"(c[0]), "+f"(c[1]), "+f"(c[2]), "+f"(c[3])
        : "r"(a0), "r"(a1), "r"(a2), "r"(a3), "r"(b0), "r"(b1));
}
// fp16 m16n8k16, fp32 accumulate (edge kernel)
__device__ __forceinline__ void mma16(float c[4],
                                      uint32_t a0, uint32_t a1, uint32_t a2, uint32_t a3,
                                      uint32_t b0, uint32_t b1) {
    asm volatile(
        "mma.sync.aligned.m16n8k16.row.col.f32.f16.f16.f32 "
        "{%0,%1,%2,%3}, {%4,%5,%6,%7}, {%8,%9}, {%0,%1,%2,%3};"
        : "+f"(c[0]), "+f"(c[1]), "+f"(c[2]), "+f"(c[3])
        : "r"(a0), "r"(a1), "r"(a2), "r"(a3), "r"(b0), "r"(b1));
}

__device__ __forceinline__ void cp16(void* dst_smem, const void* src_gmem) {
    uint32_t d = (uint32_t)__cvta_generic_to_shared(dst_smem);
    asm volatile("cp.async.cg.shared.global [%0], [%1], 16;\n"
                 :: "r"(d), "l"(src_gmem));
}
#define CP_COMMIT() asm volatile("cp.async.commit_group;\n" ::: "memory")
#define CP_WAIT0()  asm volatile("cp.async.wait_group 0;\n" ::: "memory")

// ---- K0: Wcat (tf32) + W2h/W3h fp16 fragment tables ----
// W2h word: chunk c, ksl(0..1), gtile(0..24), lane l=g*4+t, rb(0..1)
//   = half2( W2[k0][n], W2[k0+1][n] ),  k0=(2c+ksl)*16+rb*8+2t, n=gtile*8+g
__global__ void prep_weights(const float* __restrict__ fc1_w,
                             const float* __restrict__ fc2_w,
                             const float* __restrict__ fc3_w) {
    const int t1 = K1P * ABW, t2 = W2H_TOTAL, t3 = W3H_TOTAL;
    for (int i = blockIdx.x * blockDim.x + threadIdx.x; i < t1 + t2 + t3;
         i += gridDim.x * blockDim.x) {
        if (i < t1) {
            int k = i / ABW, j = i % ABW;
            float v = 0.f;
            if (k < 400) {
                if (j < 400) v = fc1_w[k * 400 + j];
                else if (j >= 416 && j < 816) v = fc1_w[(400 + k) * 400 + (j - 416)];
            }
            g_Wcat[i] = tf32r(v);
        } else if (i < t1 + t2) {
            int ii = i - t1;
            int c = ii / 3200, r2 = ii % 3200;
            int rb = r2 & 1, l = (r2 >> 1) & 31, rr = r2 >> 6;
            int gtile = rr % 25, ksl = rr / 25;
            int g = l >> 2, t = l & 3;
            int k0 = (c * 2 + ksl) * 16 + rb * 8 + 2 * t;
            int n = gtile * 8 + g;
            float f0 = (k0 < 400) ? fc2_w[k0 * 200 + n] : 0.f;
            float f1 = (k0 + 1 < 400) ? fc2_w[(k0 + 1) * 200 + n] : 0.f;
            g_W2h[ii] = pack2(f0, f1);
        } else {
            int ii = i - t1 - t2;
            int rb = ii & 1, l = (ii >> 1) & 31, rr = ii >> 6;
            int gtile = rr % 13, ks = rr / 13;
            int g = l >> 2, t = l & 3;
            int k0 = ks * 16 + rb * 8 + 2 * t;
            int n = gtile * 8 + g;
            float f0 = (k0 < 200 && n < 100) ? fc3_w[k0 * 100 + n] : 0.f;
            float f1 = (k0 + 1 < 200 && n < 100) ? fc3_w[(k0 + 1) * 100 + n] : 0.f;
            g_W3h[ii] = pack2(f0, f1);
        }
    }
}

__global__ void node_mlp(const float* __restrict__ cf,
                         const float* __restrict__ w1, const float* __restrict__ b1,
                         const float* __restrict__ w2, const float* __restrict__ b2,
                         const float* __restrict__ w3, const float* __restrict__ b3) {
    __shared__ float s_w1[256], s_b1[64], s_w2[2048], s_b2[32], s_w3[512], s_b3[16];
    int tid = threadIdx.x;
    for (int i = tid; i < 256; i += blockDim.x)  s_w1[i] = w1[i];
    for (int i = tid; i < 64; i += blockDim.x)   s_b1[i] = b1[i];
    for (int i = tid; i < 2048; i += blockDim.x) s_w2[i] = w2[i];
    for (int i = tid; i < 32; i += blockDim.x)   s_b2[i] = b2[i];
    for (int i = tid; i < 512; i += blockDim.x)  s_w3[i] = w3[i];
    for (int i = tid; i < 16; i += blockDim.x)   s_b3[i] = b3[i];
    __syncthreads();
    int n = blockIdx.x * blockDim.x + tid;
    if (n >= N_NODES) return;
    float c0 = cf[n * 4], c1 = cf[n * 4 + 1], c2 = cf[n * 4 + 2], c3 = cf[n * 4 + 3];
    float h1[64];
#pragma unroll
    for (int j = 0; j < 64; j++)
        h1[j] = fmaxf(s_b1[j] + c0 * s_w1[j] + c1 * s_w1[64 + j] + c2 * s_w1[128 + j] + c3 * s_w1[192 + j], 0.f);
    float h2[32];
    for (int j = 0; j < 32; j++) {
        float v = s_b2[j];
        for (int k = 0; k < 64; k++) v += h1[k] * s_w2[k * 32 + j];
        h2[j] = fmaxf(v, 0.f);
    }
    for (int j = 0; j < 16; j++) {
        float v = s_b3[j];
        for (int k = 0; k < 32; k++) v += h2[k] * s_w3[k * 16 + j];
        g_M[n * 16 + j] = v;
    }
}

__global__ void build_zc(const float* __restrict__ z, const float* __restrict__ esm) {
    const int total = MP * K1P;
    for (int i = blockIdx.x * blockDim.x + threadIdx.x; i < total;
         i += gridDim.x * blockDim.x) {
        int n = i / K1P, c = i % K1P;
        float v = 0.f;
        if (n < N_NODES) {
            if (c < 64) v = z[n * 64 + c];
            else if (c < 80) v = g_M[n * 16 + c - 64];
            else if (c < 400) v = esm[n * 320 + (c - 80)];
        }
        g_ZC[i] = tf32r(v);
    }
}

// ---- K3: AB = ZC @ Wcat (unchanged, tf32) ----
__global__ __launch_bounds__(256) void gemm_ab(const float* __restrict__ fc1_b) {
    __shared__ float As[64 * 36];
    __shared__ float Bs[32 * 72];
    int tid = threadIdx.x;
    int w = tid >> 5, lane = tid & 31;
    int g = lane >> 2, t = lane & 3;
    int wm = w & 3, wn = w >> 2;
    int m0 = blockIdx.y * 64, n0 = blockIdx.x * 64;
    float acc[4][4] = {};
    for (int kt = 0; kt < K1P; kt += 32) {
        for (int i = tid; i < 64 * 8; i += 256) {
            int r = i >> 3, c4 = (i & 7) * 4;
            float4 v = *(const float4*)&g_ZC[(m0 + r) * K1P + kt + c4];
            As[r * 36 + c4] = v.x; As[r * 36 + c4 + 1] = v.y;
            As[r * 36 + c4 + 2] = v.z; As[r * 36 + c4 + 3] = v.w;
        }
        for (int i = tid; i < 32 * 16; i += 256) {
            int r = i >> 4, c4 = (i & 15) * 4;
            float4 v = *(const float4*)&g_Wcat[(kt + r) * ABW + n0 + c4];
            Bs[r * 72 + c4] = v.x; Bs[r * 72 + c4 + 1] = v.y;
            Bs[r * 72 + c4 + 2] = v.z; Bs[r * 72 + c4 + 3] = v.w;
        }
        __syncthreads();
#pragma unroll
        for (int k8 = 0; k8 < 4; k8++) {
            int kk = k8 * 8, ar = wm * 16 + g;
            uint32_t a0 = __float_as_uint(As[ar * 36 + kk + t]);
            uint32_t a1 = __float_as_uint(As[(ar + 8) * 36 + kk + t]);
            uint32_t a2 = __float_as_uint(As[ar * 36 + kk + t + 4]);
            uint32_t a3 = __float_as_uint(As[(ar + 8) * 36 + kk + t + 4]);
#pragma unroll
            for (int nf = 0; nf < 4; nf++) {
                int col = wn * 32 + nf * 8 + g;
                uint32_t b0 = __float_as_uint(Bs[(kk + t) * 72 + col]);
                uint32_t b1 = __float_as_uint(Bs[(kk + t + 4) * 72 + col]);
                mma8(acc[nf], a0, a1, a2, a3, b0, b1);
            }
        }
        __syncthreads();
    }
#pragma unroll
    for (int nf = 0; nf < 4; nf++)
#pragma unroll
        for (int i = 0; i < 4; i++) {
            int r = m0 + wm * 16 + g + ((i >> 1) ? 8 : 0);
            int col = n0 + wn * 32 + nf * 8 + 2 * t + (i & 1);
            float v = acc[nf][i];
            if (col < 400) v += __ldg(&fc1_b[col]);
            g_AB[r * ABW + col] = v;
        }
}

// ============================================================================
// K4: fused edge kernel — fp16 m16n8k16, R11 pipeline.
//   fc2: K=416 (13 k32 chunks = 26 k16), N=200 (25 tiles, split {7,6,6,6})
//   fc3: K=208 padded (13 k16, zeros at 200-207), N=104 (13 tiles, {4,3,3,3})
//   smem word map:
//     h2f  [0,13728)       : 8 mtg x 13 ks x 132 (uint32 half2 A-frags)
//     h1f  [13728,17952)   : 2 x 2112
//     wb2  [17952,24352)   : 2 x 3200
//     wb3  [24352,35168)   : 10816 (whole fc3 weight table, loaded once)
//     spart[35168,35680) sw4[35680,35808) src[35808,35936) dst[35936,36064)
// ============================================================================
#define SM_H2F   0
#define SM_H1F   13728
#define H1_STRIDE 2112
#define SM_WB2   17952
#define SM_WB3   24352
#define SM_SPART 35168
#define SM_SW4   35680
#define SM_SRC   35808
#define SM_DST   35936
#define SM_WORDS 36064

__global__ __launch_bounds__(512, 1) void edge_kernel(
    const int* __restrict__ eidx,
    const float* __restrict__ b2, const float* __restrict__ b3,
    const float* __restrict__ w4, const float* __restrict__ b4v,
    float* __restrict__ out) {
    extern __shared__ float sm[];
    uint32_t* hu2 = (uint32_t*)(sm + SM_H2F);
    uint32_t* hu1 = (uint32_t*)(sm + SM_H1F);
    uint32_t* wb2 = (uint32_t*)(sm + SM_WB2);
    uint32_t* wb3 = (uint32_t*)(sm + SM_WB3);
    float* spart = sm + SM_SPART;
    float* sw4 = sm + SM_SW4;
    int* ssrc = (int*)(sm + SM_SRC);
    int* sdst = (int*)(sm + SM_DST);

    int tid = threadIdx.x;
    int w = tid >> 5, lane = tid & 31;
    int g = lane >> 2, t = lane & 3;
    int wm = w & 3, wn = w >> 2;
    int gb2 = (wn == 0) ? 0 : (7 + (wn - 1) * 6);
    int nfc2 = (wn == 0) ? 7 : 6;
    int gb3 = (wn == 0) ? 0 : (4 + (wn - 1) * 3);
    int nfc3 = (wn == 0) ? 4 : 3;
    int cb3 = gb3 * 8;
    int e0 = blockIdx.x * TILE_E;

    if (tid < TILE_E) {
        int e = e0 + tid, s = 0, d = 0;
        if (e < N_EDGES) { s = eidx[e]; d = eidx[N_EDGES + e]; }
        s = min(max(s, 0), N_NODES - 1);
        d = min(max(d, 0), N_NODES - 1);
        ssrc[tid] = s; sdst[tid] = d;
        sw4[tid] = (tid < 100) ? __ldg(&w4[tid]) : 0.f;
    }
    __syncthreads();

    // gather geometry: thread -> (edge ge, k8 slice k8g)
    int ge = tid >> 2, k8g = tid & 3;
    int gg = ge & 7, rpg = (ge >> 3) & 1, mtg_g = ge >> 4;
    int ksl_g = k8g >> 1, khalf_g = k8g & 1;
    int h1off = (mtg_g * 2 + ksl_g) * 132 + gg * 16 + khalf_g * 2 + rpg;
    const float* srowp = &g_AB[(size_t)ssrc[ge] * ABW];
    const float* drowp = &g_AB[(size_t)sdst[ge] * ABW + 416];
    int q = k8g * 8;

    float acc2[2][7][4] = {};

#define STAGE_A_STORE(buf, a0, a1, c0, c1) do { \
        uint32_t* hw = hu1 + (buf) * H1_STRIDE + h1off; \
        hw[0]  = pack2(fmaxf(a0.x + c0.x, 0.f), fmaxf(a0.y + c0.y, 0.f)); \
        hw[4]  = pack2(fmaxf(a0.z + c0.z, 0.f), fmaxf(a0.w + c0.w, 0.f)); \
        hw[8]  = pack2(fmaxf(a1.x + c1.x, 0.f), fmaxf(a1.y + c1.y, 0.f)); \
        hw[12] = pack2(fmaxf(a1.z + c1.z, 0.f), fmaxf(a1.w + c1.w, 0.f)); } while (0)

    // -------- prologue: zero h2f (covers fc3 K-pad 200..207), stage tile 0 --------
    {
        uint4 zz = make_uint4(0, 0, 0, 0);
        for (int j = tid; j < 3432; j += 512)
            ((uint4*)hu2)[j] = zz;
        float4 a0 = *(const float4*)&srowp[q];
        float4 a1 = *(const float4*)&srowp[q + 4];
        float4 c0 = *(const float4*)&drowp[q];
        float4 c1 = *(const float4*)&drowp[q + 4];
        for (int j = tid; j < 800; j += 512)
            cp16(&wb2[j * 4], &g_W2h[j * 4]);
        CP_COMMIT();
        STAGE_A_STORE(0, a0, a1, c0, c1);
        CP_WAIT0();
    }
    __syncthreads();

    // ---------------- fc2: 13 k32 chunks (2 k16 steps each) ----------------
    for (int i = 0; i < 13; i++) {
        int b = i & 1;
        float4 a0, a1, c0, c1;
        if (i < 12) {
            int kt = (i + 1) * 32;
            a0 = *(const float4*)&srowp[kt + q];
            a1 = *(const float4*)&srowp[kt + q + 4];
            c0 = *(const float4*)&drowp[kt + q];
            c1 = *(const float4*)&drowp[kt + q + 4];
            const uint32_t* wsrc = &g_W2h[(i + 1) * 3200];
            uint32_t* wdst = &wb2[(b ^ 1) * 3200];
            for (int j = tid; j < 800; j += 512)
                cp16(&wdst[j * 4], &wsrc[j * 4]);
            CP_COMMIT();
        }
        const uint32_t* hbase = hu1 + b * H1_STRIDE;
        const uint32_t* wbase = wb2 + b * 3200;
#pragma unroll
        for (int ksl = 0; ksl < 2; ksl++) {
            uint4 A0 = *(const uint4*)&hbase[((wm * 2 + 0) * 2 + ksl) * 132 + lane * 4];
            uint4 A1 = *(const uint4*)&hbase[((wm * 2 + 1) * 2 + ksl) * 132 + lane * 4];
#pragma unroll
            for (int nf = 0; nf < 7; nf++) {
                if (nf < nfc2) {
                    uint2 B = *(const uint2*)&wbase[(ksl * 25 + gb2 + nf) * 64 + lane * 2];
                    mma16(acc2[0][nf], A0.x, A0.y, A0.z, A0.w, B.x, B.y);
                    mma16(acc2[1][nf], A1.x, A1.y, A1.z, A1.w, B.x, B.y);
                }
            }
        }
        if (i < 12) {
            STAGE_A_STORE(b ^ 1, a0, a1, c0, c1);
            CP_WAIT0();
        }
        __syncthreads();
    }

    // load ALL fc3 weights (overlaps epilogue below)
    for (int j = tid; j < 2704; j += 512)
        cp16(&wb3[j * 4], &g_W3h[j * 4]);
    CP_COMMIT();

    // fc2 epilogue: bias + relu -> h2f (fp16 A-fragment order for fc3)
#pragma unroll
    for (int mt = 0; mt < 2; mt++) {
        int mtg = wm * 2 + mt;
#pragma unroll
        for (int nf = 0; nf < 7; nf++) {
            if (nf < nfc2) {
                int gt = gb2 + nf;               // global n8-tile 0..24
                int ks = gt >> 1, khalf = gt & 1;
                int c0 = gt * 8 + 2 * t;         // < 200 always
                float bv0 = __ldg(&b2[c0]), bv1 = __ldg(&b2[c0 + 1]);
                float v0 = fmaxf(acc2[mt][nf][0] + bv0, 0.f);
                float v1 = fmaxf(acc2[mt][nf][1] + bv1, 0.f);
                float v2 = fmaxf(acc2[mt][nf][2] + bv0, 0.f);
                float v3 = fmaxf(acc2[mt][nf][3] + bv1, 0.f);
                uint32_t* base = hu2 + (mtg * 13 + ks) * 132 + (g * 4 + t) * 4 + khalf * 2;
                base[0] = pack2(v0, v1);   // rp=0 (rows g)
                base[1] = pack2(v2, v3);   // rp=1 (rows g+8)
            }
        }
    }
    CP_WAIT0();
    __syncthreads();

    // ---------------- fc3: 13 k16 steps, no staging, straight-line ----------------
    float acc3[2][4][4] = {};
#pragma unroll
    for (int ks = 0; ks < 13; ks++) {
        uint4 A0 = *(const uint4*)&hu2[((wm * 2 + 0) * 13 + ks) * 132 + lane * 4];
        uint4 A1 = *(const uint4*)&hu2[((wm * 2 + 1) * 13 + ks) * 132 + lane * 4];
#pragma unroll
        for (int nf = 0; nf < 4; nf++) {
            if (nf < nfc3) {
                uint2 B = *(const uint2*)&wb3[(ks * 13 + gb3 + nf) * 64 + lane * 2];
                mma16(acc3[0][nf], A0.x, A0.y, A0.z, A0.w, B.x, B.y);
                mma16(acc3[1][nf], A1.x, A1.y, A1.z, A1.w, B.x, B.y);
            }
        }
    }

    // ---------------- fc3 epilogue + fc4 dot ----------------
    float s2[2][2] = {};
#pragma unroll
    for (int mt = 0; mt < 2; mt++) {
#pragma unroll
        for (int nf = 0; nf < 4; nf++) {
            if (nf < nfc3) {
#pragma unroll
                for (int i = 0; i < 4; i++) {
                    int col = cb3 + nf * 8 + 2 * t + (i & 1);   // 0..103
                    float v = acc3[mt][nf][i];
                    if (col < 100) v += __ldg(&b3[col]);
                    v = fmaxf(v, 0.f);
                    s2[mt][i >> 1] += v * sw4[col];             // sw4 zero-padded
                }
            }
        }
    }
#pragma unroll
    for (int mt = 0; mt < 2; mt++) {
#pragma unroll
        for (int rp = 0; rp < 2; rp++) {
            float v = s2[mt][rp];
            v += __shfl_xor_sync(0xffffffffu, v, 1);
            v += __shfl_xor_sync(0xffffffffu, v, 2);
            if (t == 0) spart[wn * 128 + wm * 32 + mt * 16 + g + 8 * rp] = v;
        }
    }
    __syncthreads();
    if (tid < TILE_E) {
        float v = spart[tid] + spart[128 + tid] + spart[256 + tid] + spart[384 + tid]
                + __ldg(&b4v[0]);
        int e = e0 + tid;
        if (e < N_EDGES) out[e] = v;
    }
}

extern "C" void kernel_launch(void* const* d_in, const int* in_sizes, int n_in,
                              void* d_out, int out_size) {
    const float* z    = (const float*)d_in[0];
    const int*   ei   = (const int*)d_in[1];
    const float* cf   = (const float*)d_in[2];
    const float* esm  = (const float*)d_in[3];
    const float* mw1  = (const float*)d_in[4];
    const float* mb1  = (const float*)d_in[5];
    const float* mw2  = (const float*)d_in[6];
    const float* mb2  = (const float*)d_in[7];
    const float* mw3  = (const float*)d_in[8];
    const float* mb3  = (const float*)d_in[9];
    const float* fc1w = (const float*)d_in[10];
    const float* fc1b = (const float*)d_in[11];
    const float* fc2w = (const float*)d_in[12];
    const float* fc2b = (const float*)d_in[13];
    const float* fc3w = (const float*)d_in[14];
    const float* fc3b = (const float*)d_in[15];
    const float* fc4w = (const float*)d_in[16];
    const float* fc4b = (const float*)d_in[17];
    float* out = (float*)d_out;

    prep_weights<<<512, 256>>>(fc1w, fc2w, fc3w);
    node_mlp<<<(N_NODES + 127) / 128, 128>>>(cf, mw1, mb1, mw2, mb2, mw3, mb3);
    build_zc<<<2048, 256>>>(z, esm);
    gemm_ab<<<dim3(13, 313), 256>>>(fc1b);

    size_t smem = (size_t)SM_WORDS * sizeof(float);   // 144256 bytes
    cudaFuncSetAttribute(edge_kernel, cudaFuncAttributeMaxDynamicSharedMemorySize, (int)smem);
    edge_kernel<<<(N_EDGES + TILE_E - 1) / TILE_E, 512, smem>>>(ei, fc2b, fc3b, fc4w, fc4b, out);
}

// round 15
// speedup vs baseline: 2.7407x; 1.1787x over previous
#include <cuda_runtime.h>
#include <cuda_fp16.h>
#include <cstdint>

#define N_NODES 20000
#define N_EDGES 500000

#define MP   20032
#define K1P  416
#define ABW  832
#define TILE_E 128

#define NMT  (MP / 16)            // 1252 m16-tiles
#define ZCF_TOTAL (NMT * 26 * 128)     // fp16 A-fragment table for fc1
#define WCH_TOTAL (26 * 104 * 64)      // fp16 B-fragment table for fc1
#define W2H_TOTAL (13 * 3200)
#define W3H_TOTAL (13 * 13 * 64)

__device__ float g_M[N_NODES * 16];
__device__ __align__(16) uint32_t g_ZCf[ZCF_TOTAL];     // zc, fp16 A-frag order
__device__ __align__(16) uint32_t g_Wch[WCH_TOTAL];     // fc1 W, fp16 B-frag order
__device__ __align__(16) float g_AB[MP * ABW];          // ~67 MB, L2-resident
__device__ __align__(16) uint32_t g_W2h[W2H_TOTAL];
__device__ __align__(16) uint32_t g_W3h[W3H_TOTAL];

__device__ __forceinline__ uint32_t pack2(float lo, float hi) {
    __half2 h = __floats2half2_rn(lo, hi);
    return *(uint32_t*)&h;
}

__device__ __forceinline__ void mma16(float c[4],
                                      uint32_t a0, uint32_t a1, uint32_t a2, uint32_t a3,
                                      uint32_t b0, uint32_t b1) {
    asm volatile(
        "mma.sync.aligned.m16n8k16.row.col.f32.f16.f16.f32 "
        "{%0,%1,%2,%3}, {%4,%5,%6,%7}, {%8,%9}, {%0,%1,%2,%3};"
        : "+f"(c[0]), "+f"(c[1]), "+f"(c[2]), "+f"(c[3])
        : "r"(a0), "r"(a1), "r"(a2), "r"(a3), "r"(b0), "r"(b1));
}

__device__ __forceinline__ void cp16(void* dst_smem, const void* src_gmem) {
    uint32_t d = (uint32_t)__cvta_generic_to_shared(dst_smem);
    asm volatile("cp.async.cg.shared.global [%0], [%1], 16;\n"
                 :: "r"(d), "l"(src_gmem));
}
#define CP_COMMIT() asm volatile("cp.async.commit_group;\n" ::: "memory")
#define CP_WAIT0()  asm volatile("cp.async.wait_group 0;\n" ::: "memory")

// ---- K0: all weight tables in fp16 fragment order ----
// g_Wch word: ks(0..25), ntile(0..103), lane(g*4+t), rb(0..1)
//   = half2( Wcat[k0][col], Wcat[k0+1][col] ), k0=ks*16+rb*8+2t, col=ntile*8+g
__global__ void prep_weights(const float* __restrict__ fc1_w,
                             const float* __restrict__ fc2_w,
                             const float* __restrict__ fc3_w) {
    const int t1 = WCH_TOTAL, t2 = W2H_TOTAL, t3 = W3H_TOTAL;
    for (int i = blockIdx.x * blockDim.x + threadIdx.x; i < t1 + t2 + t3;
         i += gridDim.x * blockDim.x) {
        if (i < t1) {
            int rb = i & 1, l = (i >> 1) & 31, rr = i >> 6;
            int nt = rr % 104, ks = rr / 104;
            int g = l >> 2, t = l & 3;
            int k0 = ks * 16 + rb * 8 + 2 * t;
            int col = nt * 8 + g;
            float f0 = 0.f, f1 = 0.f;
            if (col < 400) {
                if (k0 < 400)     f0 = fc1_w[k0 * 400 + col];
                if (k0 + 1 < 400) f1 = fc1_w[(k0 + 1) * 400 + col];
            } else if (col >= 416 && col < 816) {
                int cc = col - 416;
                if (k0 < 400)     f0 = fc1_w[(400 + k0) * 400 + cc];
                if (k0 + 1 < 400) f1 = fc1_w[(400 + k0 + 1) * 400 + cc];
            }
            g_Wch[i] = pack2(f0, f1);
        } else if (i < t1 + t2) {
            int ii = i - t1;
            int c = ii / 3200, r2 = ii % 3200;
            int rb = r2 & 1, l = (r2 >> 1) & 31, rr = r2 >> 6;
            int gtile = rr % 25, ksl = rr / 25;
            int g = l >> 2, t = l & 3;
            int k0 = (c * 2 + ksl) * 16 + rb * 8 + 2 * t;
            int n = gtile * 8 + g;
            float f0 = (k0 < 400) ? fc2_w[k0 * 200 + n] : 0.f;
            float f1 = (k0 + 1 < 400) ? fc2_w[(k0 + 1) * 200 + n] : 0.f;
            g_W2h[ii] = pack2(f0, f1);
        } else {
            int ii = i - t1 - t2;
            int rb = ii & 1, l = (ii >> 1) & 31, rr = ii >> 6;
            int gtile = rr % 13, ks = rr / 13;
            int g = l >> 2, t = l & 3;
            int k0 = ks * 16 + rb * 8 + 2 * t;
            int n = gtile * 8 + g;
            float f0 = (k0 < 200 && n < 100) ? fc3_w[k0 * 100 + n] : 0.f;
            float f1 = (k0 + 1 < 200 && n < 100) ? fc3_w[(k0 + 1) * 100 + n] : 0.f;
            g_W3h[ii] = pack2(f0, f1);
        }
    }
}

// ---- K1: tiny per-node MLP 4->64->32->16 ----
__global__ void node_mlp(const float* __restrict__ cf,
                         const float* __restrict__ w1, const float* __restrict__ b1,
                         const float* __restrict__ w2, const float* __restrict__ b2,
                         const float* __restrict__ w3, const float* __restrict__ b3) {
    __shared__ float s_w1[256], s_b1[64], s_w2[2048], s_b2[32], s_w3[512], s_b3[16];
    int tid = threadIdx.x;
    for (int i = tid; i < 256; i += blockDim.x)  s_w1[i] = w1[i];
    for (int i = tid; i < 64; i += blockDim.x)   s_b1[i] = b1[i];
    for (int i = tid; i < 2048; i += blockDim.x) s_w2[i] = w2[i];
    for (int i = tid; i < 32; i += blockDim.x)   s_b2[i] = b2[i];
    for (int i = tid; i < 512; i += blockDim.x)  s_w3[i] = w3[i];
    for (int i = tid; i < 16; i += blockDim.x)   s_b3[i] = b3[i];
    __syncthreads();
    int n = blockIdx.x * blockDim.x + tid;
    if (n >= N_NODES) return;
    float c0 = cf[n * 4], c1 = cf[n * 4 + 1], c2 = cf[n * 4 + 2], c3 = cf[n * 4 + 3];
    float h1[64];
#pragma unroll
    for (int j = 0; j < 64; j++)
        h1[j] = fmaxf(s_b1[j] + c0 * s_w1[j] + c1 * s_w1[64 + j] + c2 * s_w1[128 + j] + c3 * s_w1[192 + j], 0.f);
    float h2[32];
    for (int j = 0; j < 32; j++) {
        float v = s_b2[j];
        for (int k = 0; k < 64; k++) v += h1[k] * s_w2[k * 32 + j];
        h2[j] = fmaxf(v, 0.f);
    }
    for (int j = 0; j < 16; j++) {
        float v = s_b3[j];
        for (int k = 0; k < 32; k++) v += h2[k] * s_w3[k * 16 + j];
        g_M[n * 16 + j] = v;
    }
}

// ---- K2: assemble zc directly into fp16 A-fragment order ----
// word ii: comp=ii&3 (khalf*2+rp), lane=(ii>>2)&31, ks=(ii>>7)%26, mtile=(ii>>7)/26
__global__ void build_zc(const float* __restrict__ z, const float* __restrict__ esm) {
    for (int i = blockIdx.x * blockDim.x + threadIdx.x; i < ZCF_TOTAL;
         i += gridDim.x * blockDim.x) {
        int comp = i & 3, lane = (i >> 2) & 31;
        int rr = i >> 7;
        int ks = rr % 26, mtile = rr / 26;
        int g = lane >> 2, t = lane & 3;
        int rp = comp & 1, khalf = comp >> 1;
        int n = mtile * 16 + rp * 8 + g;
        int k0 = ks * 16 + khalf * 8 + 2 * t;
        float f0 = 0.f, f1 = 0.f;
        if (n < N_NODES) {
#pragma unroll
            for (int u = 0; u < 2; u++) {
                int c = k0 + u;
                float v = 0.f;
                if (c < 64) v = z[n * 64 + c];
                else if (c < 80) v = g_M[n * 16 + c - 64];
                else if (c < 400) v = esm[n * 320 + (c - 80)];
                if (u == 0) f0 = v; else f1 = v;
            }
        }
        g_ZCf[i] = pack2(f0, f1);
    }
}

// ---- K3: AB = ZC @ Wcat, fp16 fragment-direct, NO smem ----
__global__ __launch_bounds__(256) void gemm_ab(const float* __restrict__ fc1_b) {
    int tid = threadIdx.x;
    int w = tid >> 5, lane = tid & 31;
    int g = lane >> 2, t = lane & 3;
    int wm = w & 3, wn = w >> 2;
    int mtile = blockIdx.y * 4 + wm;
    int nb = blockIdx.x * 8 + wn * 4;        // 4 n8-tiles per warp
    float acc[4][4] = {};
    const uint4* aptr = (const uint4*)&g_ZCf[(mtile * 26) * 128 + lane * 4];
#pragma unroll 2
    for (int ks = 0; ks < 26; ks++) {
        uint4 A = aptr[ks * 32];
#pragma unroll
        for (int nf = 0; nf < 4; nf++) {
            uint2 B = *(const uint2*)&g_Wch[(ks * 104 + nb + nf) * 64 + lane * 2];
            mma16(acc[nf], A.x, A.y, A.z, A.w, B.x, B.y);
        }
    }
    int m0 = blockIdx.y * 64;
#pragma unroll
    for (int nf = 0; nf < 4; nf++)
#pragma unroll
        for (int i = 0; i < 4; i++) {
            int r = m0 + wm * 16 + g + ((i >> 1) ? 8 : 0);
            int col = (nb + nf) * 8 + 2 * t + (i & 1);
            float v = acc[nf][i];
            if (col < 400) v += __ldg(&fc1_b[col]);
            g_AB[r * ABW + col] = v;
        }
}

// ============================================================================
// K4: fused edge kernel — fp16 m16n8k16 (unchanged from R12 WIN)
// ============================================================================
#define SM_H2F   0
#define SM_H1F   13728
#define H1_STRIDE 2112
#define SM_WB2   17952
#define SM_WB3   24352
#define SM_SPART 35168
#define SM_SW4   35680
#define SM_SRC   35808
#define SM_DST   35936
#define SM_WORDS 36064

__global__ __launch_bounds__(512, 1) void edge_kernel(
    const int* __restrict__ eidx,
    const float* __restrict__ b2, const float* __restrict__ b3,
    const float* __restrict__ w4, const float* __restrict__ b4v,
    float* __restrict__ out) {
    extern __shared__ float sm[];
    uint32_t* hu2 = (uint32_t*)(sm + SM_H2F);
    uint32_t* hu1 = (uint32_t*)(sm + SM_H1F);
    uint32_t* wb2 = (uint32_t*)(sm + SM_WB2);
    uint32_t* wb3 = (uint32_t*)(sm + SM_WB3);
    float* spart = sm + SM_SPART;
    float* sw4 = sm + SM_SW4;
    int* ssrc = (int*)(sm + SM_SRC);
    int* sdst = (int*)(sm + SM_DST);

    int tid = threadIdx.x;
    int w = tid >> 5, lane = tid & 31;
    int g = lane >> 2, t = lane & 3;
    int wm = w & 3, wn = w >> 2;
    int gb2 = (wn == 0) ? 0 : (7 + (wn - 1) * 6);
    int nfc2 = (wn == 0) ? 7 : 6;
    int gb3 = (wn == 0) ? 0 : (4 + (wn - 1) * 3);
    int nfc3 = (wn == 0) ? 4 : 3;
    int cb3 = gb3 * 8;
    int e0 = blockIdx.x * TILE_E;

    if (tid < TILE_E) {
        int e = e0 + tid, s = 0, d = 0;
        if (e < N_EDGES) { s = eidx[e]; d = eidx[N_EDGES + e]; }
        s = min(max(s, 0), N_NODES - 1);
        d = min(max(d, 0), N_NODES - 1);
        ssrc[tid] = s; sdst[tid] = d;
        sw4[tid] = (tid < 100) ? __ldg(&w4[tid]) : 0.f;
    }
    __syncthreads();

    int ge = tid >> 2, k8g = tid & 3;
    int gg = ge & 7, rpg = (ge >> 3) & 1, mtg_g = ge >> 4;
    int ksl_g = k8g >> 1, khalf_g = k8g & 1;
    int h1off = (mtg_g * 2 + ksl_g) * 132 + gg * 16 + khalf_g * 2 + rpg;
    const float* srowp = &g_AB[(size_t)ssrc[ge] * ABW];
    const float* drowp = &g_AB[(size_t)sdst[ge] * ABW + 416];
    int q = k8g * 8;

    float acc2[2][7][4] = {};

#define STAGE_A_STORE(buf, a0, a1, c0, c1) do { \
        uint32_t* hw = hu1 + (buf) * H1_STRIDE + h1off; \
        hw[0]  = pack2(fmaxf(a0.x + c0.x, 0.f), fmaxf(a0.y + c0.y, 0.f)); \
        hw[4]  = pack2(fmaxf(a0.z + c0.z, 0.f), fmaxf(a0.w + c0.w, 0.f)); \
        hw[8]  = pack2(fmaxf(a1.x + c1.x, 0.f), fmaxf(a1.y + c1.y, 0.f)); \
        hw[12] = pack2(fmaxf(a1.z + c1.z, 0.f), fmaxf(a1.w + c1.w, 0.f)); } while (0)

    {
        uint4 zz = make_uint4(0, 0, 0, 0);
        for (int j = tid; j < 3432; j += 512)
            ((uint4*)hu2)[j] = zz;
        float4 a0 = *(const float4*)&srowp[q];
        float4 a1 = *(const float4*)&srowp[q + 4];
        float4 c0 = *(const float4*)&drowp[q];
        float4 c1 = *(const float4*)&drowp[q + 4];
        for (int j = tid; j < 800; j += 512)
            cp16(&wb2[j * 4], &g_W2h[j * 4]);
        CP_COMMIT();
        STAGE_A_STORE(0, a0, a1, c0, c1);
        CP_WAIT0();
    }
    __syncthreads();

    for (int i = 0; i < 13; i++) {
        int b = i & 1;
        float4 a0, a1, c0, c1;
        if (i < 12) {
            int kt = (i + 1) * 32;
            a0 = *(const float4*)&srowp[kt + q];
            a1 = *(const float4*)&srowp[kt + q + 4];
            c0 = *(const float4*)&drowp[kt + q];
            c1 = *(const float4*)&drowp[kt + q + 4];
            const uint32_t* wsrc = &g_W2h[(i + 1) * 3200];
            uint32_t* wdst = &wb2[(b ^ 1) * 3200];
            for (int j = tid; j < 800; j += 512)
                cp16(&wdst[j * 4], &wsrc[j * 4]);
            CP_COMMIT();
        }
        const uint32_t* hbase = hu1 + b * H1_STRIDE;
        const uint32_t* wbase = wb2 + b * 3200;
#pragma unroll
        for (int ksl = 0; ksl < 2; ksl++) {
            uint4 A0 = *(const uint4*)&hbase[((wm * 2 + 0) * 2 + ksl) * 132 + lane * 4];
            uint4 A1 = *(const uint4*)&hbase[((wm * 2 + 1) * 2 + ksl) * 132 + lane * 4];
#pragma unroll
            for (int nf = 0; nf < 7; nf++) {
                if (nf < nfc2) {
                    uint2 B = *(const uint2*)&wbase[(ksl * 25 + gb2 + nf) * 64 + lane * 2];
                    mma16(acc2[0][nf], A0.x, A0.y, A0.z, A0.w, B.x, B.y);
                    mma16(acc2[1][nf], A1.x, A1.y, A1.z, A1.w, B.x, B.y);
                }
            }
        }
        if (i < 12) {
            STAGE_A_STORE(b ^ 1, a0, a1, c0, c1);
            CP_WAIT0();
        }
        __syncthreads();
    }

    for (int j = tid; j < 2704; j += 512)
        cp16(&wb3[j * 4], &g_W3h[j * 4]);
    CP_COMMIT();

#pragma unroll
    for (int mt = 0; mt < 2; mt++) {
        int mtg = wm * 2 + mt;
#pragma unroll
        for (int nf = 0; nf < 7; nf++) {
            if (nf < nfc2) {
                int gt = gb2 + nf;
                int ks = gt >> 1, khalf = gt & 1;
                int c0 = gt * 8 + 2 * t;
                float bv0 = __ldg(&b2[c0]), bv1 = __ldg(&b2[c0 + 1]);
                float v0 = fmaxf(acc2[mt][nf][0] + bv0, 0.f);
                float v1 = fmaxf(acc2[mt][nf][1] + bv1, 0.f);
                float v2 = fmaxf(acc2[mt][nf][2] + bv0, 0.f);
                float v3 = fmaxf(acc2[mt][nf][3] + bv1, 0.f);
                uint32_t* base = hu2 + (mtg * 13 + ks) * 132 + (g * 4 + t) * 4 + khalf * 2;
                base[0] = pack2(v0, v1);
                base[1] = pack2(v2, v3);
            }
        }
    }
    CP_WAIT0();
    __syncthreads();

    float acc3[2][4][4] = {};
#pragma unroll
    for (int ks = 0; ks < 13; ks++) {
        uint4 A0 = *(const uint4*)&hu2[((wm * 2 + 0) * 13 + ks) * 132 + lane * 4];
        uint4 A1 = *(const uint4*)&hu2[((wm * 2 + 1) * 13 + ks) * 132 + lane * 4];
#pragma unroll
        for (int nf = 0; nf < 4; nf++) {
            if (nf < nfc3) {
                uint2 B = *(const uint2*)&wb3[(ks * 13 + gb3 + nf) * 64 + lane * 2];
                mma16(acc3[0][nf], A0.x, A0.y, A0.z, A0.w, B.x, B.y);
                mma16(acc3[1][nf], A1.x, A1.y, A1.z, A1.w, B.x, B.y);
            }
        }
    }

    float s2[2][2] = {};
#pragma unroll
    for (int mt = 0; mt < 2; mt++) {
#pragma unroll
        for (int nf = 0; nf < 4; nf++) {
            if (nf < nfc3) {
#pragma unroll
                for (int i = 0; i < 4; i++) {
                    int col = cb3 + nf * 8 + 2 * t + (i & 1);
                    float v = acc3[mt][nf][i];
                    if (col < 100) v += __ldg(&b3[col]);
                    v = fmaxf(v, 0.f);
                    s2[mt][i >> 1] += v * sw4[col];
                }
            }
        }
    }
#pragma unroll
    for (int mt = 0; mt < 2; mt++) {
#pragma unroll
        for (int rp = 0; rp < 2; rp++) {
            float v = s2[mt][rp];
            v += __shfl_xor_sync(0xffffffffu, v, 1);
            v += __shfl_xor_sync(0xffffffffu, v, 2);
            if (t == 0) spart[wn * 128 + wm * 32 + mt * 16 + g + 8 * rp] = v;
        }
    }
    __syncthreads();
    if (tid < TILE_E) {
        float v = spart[tid] + spart[128 + tid] + spart[256 + tid] + spart[384 + tid]
                + __ldg(&b4v[0]);
        int e = e0 + tid;
        if (e < N_EDGES) out[e] = v;
    }
}

extern "C" void kernel_launch(void* const* d_in, const int* in_sizes, int n_in,
                              void* d_out, int out_size) {
    const float* z    = (const float*)d_in[0];
    const int*   ei   = (const int*)d_in[1];
    const float* cf   = (const float*)d_in[2];
    const float* esm  = (const float*)d_in[3];
    const float* mw1  = (const float*)d_in[4];
    const float* mb1  = (const float*)d_in[5];
    const float* mw2  = (const float*)d_in[6];
    const float* mb2  = (const float*)d_in[7];
    const float* mw3  = (const float*)d_in[8];
    const float* mb3  = (const float*)d_in[9];
    const float* fc1w = (const float*)d_in[10];
    const float* fc1b = (const float*)d_in[11];
    const float* fc2w = (const float*)d_in[12];
    const float* fc2b = (const float*)d_in[13];
    const float* fc3w = (const float*)d_in[14];
    const float* fc3b = (const float*)d_in[15];
    const float* fc4w = (const float*)d_in[16];
    const float* fc4b = (const float*)d_in[17];
    float* out = (float*)d_out;

    prep_weights<<<512, 256>>>(fc1w, fc2w, fc3w);
    node_mlp<<<(N_NODES + 127) / 128, 128>>>(cf, mw1, mb1, mw2, mb2, mw3, mb3);
    build_zc<<<2048, 256>>>(z, esm);
    gemm_ab<<<dim3(13, 313), 256>>>(fc1b);

    size_t smem = (size_t)SM_WORDS * sizeof(float);   // 144256 bytes
    cudaFuncSetAttribute(edge_kernel, cudaFuncAttributeMaxDynamicSharedMemorySize, (int)smem);
    edge_kernel<<<(N_EDGES + TILE_E - 1) / TILE_E, 512, smem>>>(ei, fc2b, fc3b, fc4w, fc4b, out);
}

// round 16
// speedup vs baseline: 3.0584x; 1.1159x over previous
#include <cuda_runtime.h>
#include <cuda_fp16.h>
#include <cstdint>

#define N_NODES 20000
#define N_EDGES 500000

#define MP   20032
#define TILE_E 128
#define ABWW 416                  // AB row stride in WORDS (half2): A words [0,208), B words [208,416)

#define NMT  (MP / 16)
#define ZCF_TOTAL (NMT * 26 * 128)
#define WCH_TOTAL (26 * 104 * 64)
#define W2H_TOTAL (13 * 3200)
#define W3H_TOTAL (13 * 13 * 64)

__device__ float g_M[N_NODES * 16];
__device__ __align__(16) uint32_t g_ZCf[ZCF_TOTAL];
__device__ __align__(16) uint32_t g_Wch[WCH_TOTAL];
__device__ __align__(16) uint32_t g_ABh[MP * ABWW];     // fp16 AB table, ~33 MB
__device__ __align__(16) uint32_t g_W2h[W2H_TOTAL];
__device__ __align__(16) uint32_t g_W3h[W3H_TOTAL];

__device__ __forceinline__ uint32_t pack2(float lo, float hi) {
    __half2 h = __floats2half2_rn(lo, hi);
    return *(uint32_t*)&h;
}
__device__ __forceinline__ uint32_t hadd_relu2(uint32_t a, uint32_t b) {
    __half2 ha = *(__half2*)&a, hb = *(__half2*)&b;
    __half2 s = __hmax2(__hadd2(ha, hb), __float2half2_rn(0.f));
    return *(uint32_t*)&s;
}

__device__ __forceinline__ void mma16(float c[4],
                                      uint32_t a0, uint32_t a1, uint32_t a2, uint32_t a3,
                                      uint32_t b0, uint32_t b1) {
    asm volatile(
        "mma.sync.aligned.m16n8k16.row.col.f32.f16.f16.f32 "
        "{%0,%1,%2,%3}, {%4,%5,%6,%7}, {%8,%9}, {%0,%1,%2,%3};"
        : "+f"(c[0]), "+f"(c[1]), "+f"(c[2]), "+f"(c[3])
        : "r"(a0), "r"(a1), "r"(a2), "r"(a3), "r"(b0), "r"(b1));
}

__device__ __forceinline__ void cp16(void* dst_smem, const void* src_gmem) {
    uint32_t d = (uint32_t)__cvta_generic_to_shared(dst_smem);
    asm volatile("cp.async.cg.shared.global [%0], [%1], 16;\n"
                 :: "r"(d), "l"(src_gmem));
}
#define CP_COMMIT() asm volatile("cp.async.commit_group;\n" ::: "memory")
#define CP_WAIT0()  asm volatile("cp.async.wait_group 0;\n" ::: "memory")

// ---- K0: all weight tables in fp16 fragment order (unchanged from R15) ----
__global__ void prep_weights(const float* __restrict__ fc1_w,
                             const float* __restrict__ fc2_w,
                             const float* __restrict__ fc3_w) {
    const int t1 = WCH_TOTAL, t2 = W2H_TOTAL, t3 = W3H_TOTAL;
    for (int i = blockIdx.x * blockDim.x + threadIdx.x; i < t1 + t2 + t3;
         i += gridDim.x * blockDim.x) {
        if (i < t1) {
            int rb = i & 1, l = (i >> 1) & 31, rr = i >> 6;
            int nt = rr % 104, ks = rr / 104;
            int g = l >> 2, t = l & 3;
            int k0 = ks * 16 + rb * 8 + 2 * t;
            int col = nt * 8 + g;
            float f0 = 0.f, f1 = 0.f;
            if (col < 400) {
                if (k0 < 400)     f0 = fc1_w[k0 * 400 + col];
                if (k0 + 1 < 400) f1 = fc1_w[(k0 + 1) * 400 + col];
            } else if (col >= 416 && col < 816) {
                int cc = col - 416;
                if (k0 < 400)     f0 = fc1_w[(400 + k0) * 400 + cc];
                if (k0 + 1 < 400) f1 = fc1_w[(400 + k0 + 1) * 400 + cc];
            }
            g_Wch[i] = pack2(f0, f1);
        } else if (i < t1 + t2) {
            int ii = i - t1;
            int c = ii / 3200, r2 = ii % 3200;
            int rb = r2 & 1, l = (r2 >> 1) & 31, rr = r2 >> 6;
            int gtile = rr % 25, ksl = rr / 25;
            int g = l >> 2, t = l & 3;
            int k0 = (c * 2 + ksl) * 16 + rb * 8 + 2 * t;
            int n = gtile * 8 + g;
            float f0 = (k0 < 400) ? fc2_w[k0 * 200 + n] : 0.f;
            float f1 = (k0 + 1 < 400) ? fc2_w[(k0 + 1) * 200 + n] : 0.f;
            g_W2h[ii] = pack2(f0, f1);
        } else {
            int ii = i - t1 - t2;
            int rb = ii & 1, l = (ii >> 1) & 31, rr = ii >> 6;
            int gtile = rr % 13, ks = rr / 13;
            int g = l >> 2, t = l & 3;
            int k0 = ks * 16 + rb * 8 + 2 * t;
            int n = gtile * 8 + g;
            float f0 = (k0 < 200 && n < 100) ? fc3_w[k0 * 100 + n] : 0.f;
            float f1 = (k0 + 1 < 200 && n < 100) ? fc3_w[(k0 + 1) * 100 + n] : 0.f;
            g_W3h[ii] = pack2(f0, f1);
        }
    }
}

// ---- K1: tiny per-node MLP ----
__global__ void node_mlp(const float* __restrict__ cf,
                         const float* __restrict__ w1, const float* __restrict__ b1,
                         const float* __restrict__ w2, const float* __restrict__ b2,
                         const float* __restrict__ w3, const float* __restrict__ b3) {
    __shared__ float s_w1[256], s_b1[64], s_w2[2048], s_b2[32], s_w3[512], s_b3[16];
    int tid = threadIdx.x;
    for (int i = tid; i < 256; i += blockDim.x)  s_w1[i] = w1[i];
    for (int i = tid; i < 64; i += blockDim.x)   s_b1[i] = b1[i];
    for (int i = tid; i < 2048; i += blockDim.x) s_w2[i] = w2[i];
    for (int i = tid; i < 32; i += blockDim.x)   s_b2[i] = b2[i];
    for (int i = tid; i < 512; i += blockDim.x)  s_w3[i] = w3[i];
    for (int i = tid; i < 16; i += blockDim.x)   s_b3[i] = b3[i];
    __syncthreads();
    int n = blockIdx.x * blockDim.x + tid;
    if (n >= N_NODES) return;
    float c0 = cf[n * 4], c1 = cf[n * 4 + 1], c2 = cf[n * 4 + 2], c3 = cf[n * 4 + 3];
    float h1[64];
#pragma unroll
    for (int j = 0; j < 64; j++)
        h1[j] = fmaxf(s_b1[j] + c0 * s_w1[j] + c1 * s_w1[64 + j] + c2 * s_w1[128 + j] + c3 * s_w1[192 + j], 0.f);
    float h2[32];
    for (int j = 0; j < 32; j++) {
        float v = s_b2[j];
        for (int k = 0; k < 64; k++) v += h1[k] * s_w2[k * 32 + j];
        h2[j] = fmaxf(v, 0.f);
    }
    for (int j = 0; j < 16; j++) {
        float v = s_b3[j];
        for (int k = 0; k < 32; k++) v += h2[k] * s_w3[k * 16 + j];
        g_M[n * 16 + j] = v;
    }
}

// ---- K2: assemble zc directly into fp16 A-fragment order ----
__global__ void build_zc(const float* __restrict__ z, const float* __restrict__ esm) {
    for (int i = blockIdx.x * blockDim.x + threadIdx.x; i < ZCF_TOTAL;
         i += gridDim.x * blockDim.x) {
        int comp = i & 3, lane = (i >> 2) & 31;
        int rr = i >> 7;
        int ks = rr % 26, mtile = rr / 26;
        int g = lane >> 2, t = lane & 3;
        int rp = comp & 1, khalf = comp >> 1;
        int n = mtile * 16 + rp * 8 + g;
        int k0 = ks * 16 + khalf * 8 + 2 * t;
        float f0 = 0.f, f1 = 0.f;
        if (n < N_NODES) {
#pragma unroll
            for (int u = 0; u < 2; u++) {
                int c = k0 + u;
                float v = 0.f;
                if (c < 64) v = z[n * 64 + c];
                else if (c < 80) v = g_M[n * 16 + c - 64];
                else if (c < 400) v = esm[n * 320 + (c - 80)];
                if (u == 0) f0 = v; else f1 = v;
            }
        }
        g_ZCf[i] = pack2(f0, f1);
    }
}

// ---- K3: AB = ZC @ Wcat, fp16 fragment-direct, fp16 output ----
__global__ __launch_bounds__(256) void gemm_ab(const float* __restrict__ fc1_b) {
    int tid = threadIdx.x;
    int w = tid >> 5, lane = tid & 31;
    int g = lane >> 2, t = lane & 3;
    int wm = w & 3, wn = w >> 2;
    int mtile = blockIdx.y * 4 + wm;
    int nb = blockIdx.x * 8 + wn * 4;
    float acc[4][4] = {};
    const uint4* aptr = (const uint4*)&g_ZCf[(mtile * 26) * 128 + lane * 4];
#pragma unroll 2
    for (int ks = 0; ks < 26; ks++) {
        uint4 A = aptr[ks * 32];
#pragma unroll
        for (int nf = 0; nf < 4; nf++) {
            uint2 B = *(const uint2*)&g_Wch[(ks * 104 + nb + nf) * 64 + lane * 2];
            mma16(acc[nf], A.x, A.y, A.z, A.w, B.x, B.y);
        }
    }
    int m0 = blockIdx.y * 64;
    int r = m0 + wm * 16 + g;
#pragma unroll
    for (int nf = 0; nf < 4; nf++) {
        int gt = nb + nf;                       // global n8-tile 0..103
        int wi = (gt < 52) ? (gt * 4 + t) : (208 + (gt - 52) * 4 + t);
        float b0v = 0.f, b1v = 0.f;
        if (gt < 52) {
            int col = gt * 8 + 2 * t;
            if (col < 400)     b0v = __ldg(&fc1_b[col]);
            if (col + 1 < 400) b1v = __ldg(&fc1_b[col + 1]);
        }
        g_ABh[r * ABWW + wi]       = pack2(acc[nf][0] + b0v, acc[nf][1] + b1v);
        g_ABh[(r + 8) * ABWW + wi] = pack2(acc[nf][2] + b0v, acc[nf][3] + b1v);
    }
}

// ============================================================================
// K4: fused edge kernel — fp16 everywhere; AB gathered as half2 words
// ============================================================================
#define SM_H2F   0
#define SM_H1F   13728
#define H1_STRIDE 2112
#define SM_WB2   17952
#define SM_WB3   24352
#define SM_SPART 35168
#define SM_SW4   35680
#define SM_SRC   35808
#define SM_DST   35936
#define SM_WORDS 36064

__global__ __launch_bounds__(512, 1) void edge_kernel(
    const int* __restrict__ eidx,
    const float* __restrict__ b2, const float* __restrict__ b3,
    const float* __restrict__ w4, const float* __restrict__ b4v,
    float* __restrict__ out) {
    extern __shared__ float sm[];
    uint32_t* hu2 = (uint32_t*)(sm + SM_H2F);
    uint32_t* hu1 = (uint32_t*)(sm + SM_H1F);
    uint32_t* wb2 = (uint32_t*)(sm + SM_WB2);
    uint32_t* wb3 = (uint32_t*)(sm + SM_WB3);
    float* spart = sm + SM_SPART;
    float* sw4 = sm + SM_SW4;
    int* ssrc = (int*)(sm + SM_SRC);
    int* sdst = (int*)(sm + SM_DST);

    int tid = threadIdx.x;
    int w = tid >> 5, lane = tid & 31;
    int g = lane >> 2, t = lane & 3;
    int wm = w & 3, wn = w >> 2;
    int gb2 = (wn == 0) ? 0 : (7 + (wn - 1) * 6);
    int nfc2 = (wn == 0) ? 7 : 6;
    int gb3 = (wn == 0) ? 0 : (4 + (wn - 1) * 3);
    int nfc3 = (wn == 0) ? 4 : 3;
    int cb3 = gb3 * 8;
    int e0 = blockIdx.x * TILE_E;

    if (tid < TILE_E) {
        int e = e0 + tid, s = 0, d = 0;
        if (e < N_EDGES) { s = eidx[e]; d = eidx[N_EDGES + e]; }
        s = min(max(s, 0), N_NODES - 1);
        d = min(max(d, 0), N_NODES - 1);
        ssrc[tid] = s; sdst[tid] = d;
        sw4[tid] = (tid < 100) ? __ldg(&w4[tid]) : 0.f;
    }
    __syncthreads();

    // gather geometry: thread -> (edge ge, k8 slice k8g); fp16 words
    int ge = tid >> 2, k8g = tid & 3;
    int gg = ge & 7, rpg = (ge >> 3) & 1, mtg_g = ge >> 4;
    int ksl_g = k8g >> 1, khalf_g = k8g & 1;
    int h1off = (mtg_g * 2 + ksl_g) * 132 + gg * 16 + khalf_g * 2 + rpg;
    const uint32_t* srowp = &g_ABh[(size_t)ssrc[ge] * ABWW];
    const uint32_t* drowp = &g_ABh[(size_t)sdst[ge] * ABWW + 208];
    int q2 = k8g * 4;    // word offset within 16-word k32 chunk

    float acc2[2][7][4] = {};

#define STAGE_A_STORE(buf, A, C) do { \
        uint32_t* hw = hu1 + (buf) * H1_STRIDE + h1off; \
        hw[0]  = hadd_relu2(A.x, C.x); \
        hw[4]  = hadd_relu2(A.y, C.y); \
        hw[8]  = hadd_relu2(A.z, C.z); \
        hw[12] = hadd_relu2(A.w, C.w); } while (0)

    // -------- prologue: zero h2f (fc3 K-pad), stage tile 0 --------
    {
        uint4 zz = make_uint4(0, 0, 0, 0);
        for (int j = tid; j < 3432; j += 512)
            ((uint4*)hu2)[j] = zz;
        uint4 A = *(const uint4*)&srowp[q2];
        uint4 C = *(const uint4*)&drowp[q2];
        for (int j = tid; j < 800; j += 512)
            cp16(&wb2[j * 4], &g_W2h[j * 4]);
        CP_COMMIT();
        STAGE_A_STORE(0, A, C);
        CP_WAIT0();
    }
    __syncthreads();

    // ---------------- fc2: 13 k32 chunks (2 k16 steps each) ----------------
    for (int i = 0; i < 13; i++) {
        int b = i & 1;
        uint4 A, C;
        if (i < 12) {
            int kt2 = (i + 1) * 16;
            A = *(const uint4*)&srowp[kt2 + q2];
            C = *(const uint4*)&drowp[kt2 + q2];
            const uint32_t* wsrc = &g_W2h[(i + 1) * 3200];
            uint32_t* wdst = &wb2[(b ^ 1) * 3200];
            for (int j = tid; j < 800; j += 512)
                cp16(&wdst[j * 4], &wsrc[j * 4]);
            CP_COMMIT();
        }
        const uint32_t* hbase = hu1 + b * H1_STRIDE;
        const uint32_t* wbase = wb2 + b * 3200;
#pragma unroll
        for (int ksl = 0; ksl < 2; ksl++) {
            uint4 A0 = *(const uint4*)&hbase[((wm * 2 + 0) * 2 + ksl) * 132 + lane * 4];
            uint4 A1 = *(const uint4*)&hbase[((wm * 2 + 1) * 2 + ksl) * 132 + lane * 4];
#pragma unroll
            for (int nf = 0; nf < 7; nf++) {
                if (nf < nfc2) {
                    uint2 B = *(const uint2*)&wbase[(ksl * 25 + gb2 + nf) * 64 + lane * 2];
                    mma16(acc2[0][nf], A0.x, A0.y, A0.z, A0.w, B.x, B.y);
                    mma16(acc2[1][nf], A1.x, A1.y, A1.z, A1.w, B.x, B.y);
                }
            }
        }
        if (i < 12) {
            STAGE_A_STORE(b ^ 1, A, C);
            CP_WAIT0();
        }
        __syncthreads();
    }

    // load ALL fc3 weights (overlaps epilogue below)
    for (int j = tid; j < 2704; j += 512)
        cp16(&wb3[j * 4], &g_W3h[j * 4]);
    CP_COMMIT();

    // fc2 epilogue: bias + relu -> h2f (fp16 A-fragment order for fc3)
#pragma unroll
    for (int mt = 0; mt < 2; mt++) {
        int mtg = wm * 2 + mt;
#pragma unroll
        for (int nf = 0; nf < 7; nf++) {
            if (nf < nfc2) {
                int gt = gb2 + nf;
                int ks = gt >> 1, khalf = gt & 1;
                int c0 = gt * 8 + 2 * t;
                float bv0 = __ldg(&b2[c0]), bv1 = __ldg(&b2[c0 + 1]);
                float v0 = fmaxf(acc2[mt][nf][0] + bv0, 0.f);
                float v1 = fmaxf(acc2[mt][nf][1] + bv1, 0.f);
                float v2 = fmaxf(acc2[mt][nf][2] + bv0, 0.f);
                float v3 = fmaxf(acc2[mt][nf][3] + bv1, 0.f);
                uint32_t* base = hu2 + (mtg * 13 + ks) * 132 + (g * 4 + t) * 4 + khalf * 2;
                base[0] = pack2(v0, v1);
                base[1] = pack2(v2, v3);
            }
        }
    }
    CP_WAIT0();
    __syncthreads();

    // ---------------- fc3: 13 k16 steps, straight-line ----------------
    float acc3[2][4][4] = {};
#pragma unroll
    for (int ks = 0; ks < 13; ks++) {
        uint4 A0 = *(const uint4*)&hu2[((wm * 2 + 0) * 13 + ks) * 132 + lane * 4];
        uint4 A1 = *(const uint4*)&hu2[((wm * 2 + 1) * 13 + ks) * 132 + lane * 4];
#pragma unroll
        for (int nf = 0; nf < 4; nf++) {
            if (nf < nfc3) {
                uint2 B = *(const uint2*)&wb3[(ks * 13 + gb3 + nf) * 64 + lane * 2];
                mma16(acc3[0][nf], A0.x, A0.y, A0.z, A0.w, B.x, B.y);
                mma16(acc3[1][nf], A1.x, A1.y, A1.z, A1.w, B.x, B.y);
            }
        }
    }

    // ---------------- fc3 epilogue + fc4 dot ----------------
    float s2[2][2] = {};
#pragma unroll
    for (int mt = 0; mt < 2; mt++) {
#pragma unroll
        for (int nf = 0; nf < 4; nf++) {
            if (nf < nfc3) {
#pragma unroll
                for (int i = 0; i < 4; i++) {
                    int col = cb3 + nf * 8 + 2 * t + (i & 1);
                    float v = acc3[mt][nf][i];
                    if (col < 100) v += __ldg(&b3[col]);
                    v = fmaxf(v, 0.f);
                    s2[mt][i >> 1] += v * sw4[col];
                }
            }
        }
    }
#pragma unroll
    for (int mt = 0; mt < 2; mt++) {
#pragma unroll
        for (int rp = 0; rp < 2; rp++) {
            float v = s2[mt][rp];
            v += __shfl_xor_sync(0xffffffffu, v, 1);
            v += __shfl_xor_sync(0xffffffffu, v, 2);
            if (t == 0) spart[wn * 128 + wm * 32 + mt * 16 + g + 8 * rp] = v;
        }
    }
    __syncthreads();
    if (tid < TILE_E) {
        float v = spart[tid] + spart[128 + tid] + spart[256 + tid] + spart[384 + tid]
                + __ldg(&b4v[0]);
        int e = e0 + tid;
        if (e < N_EDGES) out[e] = v;
    }
}

extern "C" void kernel_launch(void* const* d_in, const int* in_sizes, int n_in,
                              void* d_out, int out_size) {
    const float* z    = (const float*)d_in[0];
    const int*   ei   = (const int*)d_in[1];
    const float* cf   = (const float*)d_in[2];
    const float* esm  = (const float*)d_in[3];
    const float* mw1  = (const float*)d_in[4];
    const float* mb1  = (const float*)d_in[5];
    const float* mw2  = (const float*)d_in[6];
    const float* mb2  = (const float*)d_in[7];
    const float* mw3  = (const float*)d_in[8];
    const float* mb3  = (const float*)d_in[9];
    const float* fc1w = (const float*)d_in[10];
    const float* fc1b = (const float*)d_in[11];
    const float* fc2w = (const float*)d_in[12];
    const float* fc2b = (const float*)d_in[13];
    const float* fc3w = (const float*)d_in[14];
    const float* fc3b = (const float*)d_in[15];
    const float* fc4w = (const float*)d_in[16];
    const float* fc4b = (const float*)d_in[17];
    float* out = (float*)d_out;

    prep_weights<<<512, 256>>>(fc1w, fc2w, fc3w);
    node_mlp<<<(N_NODES + 127) / 128, 128>>>(cf, mw1, mb1, mw2, mb2, mw3, mb3);
    build_zc<<<2048, 256>>>(z, esm);
    gemm_ab<<<dim3(13, 313), 256>>>(fc1b);

    size_t smem = (size_t)SM_WORDS * sizeof(float);   // 144256 bytes
    cudaFuncSetAttribute(edge_kernel, cudaFuncAttributeMaxDynamicSharedMemorySize, (int)smem);
    edge_kernel<<<(N_EDGES + TILE_E - 1) / TILE_E, 512, smem>>>(ei, fc2b, fc3b, fc4w, fc4b, out);
}